// round 1
// baseline (speedup 1.0000x reference)
#include <cuda_runtime.h>
#include <math.h>

// ---------------- problem constants ----------------
#define BC    32          // B*C
#define NSEQ  1024
#define DMODEL 256
#define NHEAD 8
#define DHEAD 32
#define HID   768
#define NEDGE 8192
#define LLOG  256
#define NTOK  (BC*NSEQ)   // 32768
#define NTOKL (BC*LLOG)   // 8192

// ---------------- scratch (__device__ globals; no allocs) ----------------
__device__ float g_buf1[NTOK*HID];   // qkv / t1
__device__ float g_buf2[NTOK*HID];   // t3 ; attn_out lives in first NTOK*DMODEL
__device__ float g_xn  [NTOK*DMODEL];
__device__ float g_a   [NTOK*DMODEL];
__device__ float g_x2  [NTOK*DMODEL];
__device__ float g_x3  [NTOK*DMODEL];
__device__ float g_l   [NTOKL*DMODEL];
__device__ float g_l2  [NTOKL*DMODEL];
__device__ int   g_start[LLOG+1];
__device__ int   g_order[NEDGE];

// ---------------- RMS norm: warp per token ----------------
__global__ __launch_bounds__(256) void rms_kernel(
    const float* __restrict__ x, const float* __restrict__ w,
    float* __restrict__ y)
{
    int tok  = blockIdx.x*8 + (threadIdx.x >> 5);
    int lane = threadIdx.x & 31;
    const float* xp = x + (size_t)tok*DMODEL;
    float4 a = *(const float4*)(xp + lane*4);
    float4 b = *(const float4*)(xp + 128 + lane*4);
    float ss = a.x*a.x + a.y*a.y + a.z*a.z + a.w*a.w
             + b.x*b.x + b.y*b.y + b.z*b.z + b.w*b.w;
#pragma unroll
    for (int off=16; off; off>>=1) ss += __shfl_xor_sync(0xffffffffu, ss, off);
    float r = rsqrtf(ss*(1.0f/DMODEL) + 1e-5f);
    float4 wa = *(const float4*)(w + lane*4);
    float4 wb = *(const float4*)(w + 128 + lane*4);
    float* yp = y + (size_t)tok*DMODEL;
    float4 oa = make_float4(a.x*r*wa.x, a.y*r*wa.y, a.z*r*wa.z, a.w*r*wa.w);
    float4 ob = make_float4(b.x*r*wb.x, b.y*r*wb.y, b.z*r*wb.z, b.w*r*wb.w);
    *(float4*)(yp + lane*4)       = oa;
    *(float4*)(yp + 128 + lane*4) = ob;
}

// ---------------- GEMM: C[M,N] = A[M,K] @ W[N,K]^T (+bias)(+resid)(tanh) ----
// BM=128 BN=64 BK=16, 256 threads, 8x4 micro-tile.
// EPI: 0 = (+bias), 1 = (+bias)+resid, 2 = tanh((+bias)+resid)
#define GBM 128
#define GBN 64
#define GBK 16

template<int EPI>
__global__ __launch_bounds__(256) void gemm_kernel(
    const float* __restrict__ A, const float* __restrict__ W,
    const float* __restrict__ bias, const float* __restrict__ resid,
    float* __restrict__ C, int M, int Nn, int K)
{
    __shared__ float As[GBK][GBM];
    __shared__ float Ws[GBK][GBN];
    int bm = blockIdx.y * GBM;
    int bn = blockIdx.x * GBN;
    int t  = threadIdx.x;
    int ty = t >> 4, tx = t & 15;      // 16x16 thread grid

    float acc[8][4];
#pragma unroll
    for (int i=0;i<8;i++)
#pragma unroll
        for (int j=0;j<4;j++) acc[i][j]=0.f;

    for (int k0 = 0; k0 < K; k0 += GBK) {
        // load A tile 128x16 (512 float4)
#pragma unroll
        for (int r=0;r<2;r++) {
            int f = t + r*256;
            int row = f >> 2, c4 = (f & 3) << 2;
            float4 v = *(const float4*)(A + (size_t)(bm+row)*K + k0 + c4);
            As[c4+0][row]=v.x; As[c4+1][row]=v.y; As[c4+2][row]=v.z; As[c4+3][row]=v.w;
        }
        // load W tile 64x16 (256 float4)
        {
            int row = t >> 2, c4 = (t & 3) << 2;
            float4 v = *(const float4*)(W + (size_t)(bn+row)*K + k0 + c4);
            Ws[c4+0][row]=v.x; Ws[c4+1][row]=v.y; Ws[c4+2][row]=v.z; Ws[c4+3][row]=v.w;
        }
        __syncthreads();
#pragma unroll
        for (int kk=0; kk<GBK; kk++) {
            float4 a0 = *(const float4*)&As[kk][ty*8];
            float4 a1 = *(const float4*)&As[kk][ty*8+4];
            float4 b0 = *(const float4*)&Ws[kk][tx*4];
            float av[8] = {a0.x,a0.y,a0.z,a0.w,a1.x,a1.y,a1.z,a1.w};
            float bv[4] = {b0.x,b0.y,b0.z,b0.w};
#pragma unroll
            for (int i=0;i<8;i++)
#pragma unroll
                for (int j=0;j<4;j++) acc[i][j] += av[i]*bv[j];
        }
        __syncthreads();
    }

    float4 bb = make_float4(0,0,0,0);
    if (bias) bb = *(const float4*)(bias + bn + tx*4);
#pragma unroll
    for (int i=0;i<8;i++) {
        int m = bm + ty*8 + i;
        size_t idx = (size_t)m*Nn + bn + tx*4;
        float4 c = make_float4(acc[i][0]+bb.x, acc[i][1]+bb.y,
                               acc[i][2]+bb.z, acc[i][3]+bb.w);
        if (EPI >= 1) {
            float4 rr = *(const float4*)(resid + idx);
            c.x += rr.x; c.y += rr.y; c.z += rr.z; c.w += rr.w;
        }
        if (EPI == 2) { c.x=tanhf(c.x); c.y=tanhf(c.y); c.z=tanhf(c.z); c.w=tanhf(c.w); }
        *(float4*)(C + idx) = c;
    }
}

// ---------------- flash attention: fp32, 64q x 64kv tiles ----------------
__global__ __launch_bounds__(256) void attn_kernel(
    const float* __restrict__ qkv, float* __restrict__ out)
{
    int qt = blockIdx.x, h = blockIdx.y, bc = blockIdx.z;
    __shared__ float Qs[64][33];
    __shared__ float Ks[64][33];
    __shared__ float Vs[64][33];
    __shared__ float Ss[64][64];
    __shared__ float m_run[64], l_run[64], alpha_s[64];

    int t = threadIdx.x;
    int warp = t >> 5, lane = t & 31;
    const float scale = 0.17677669529663687f;  // 1/sqrt(32)

    // load Q tile (64 x 32) : 512 float4
#pragma unroll
    for (int r=0;r<2;r++) {
        int f = t + r*256;
        int q = f >> 3, d4 = (f & 7) << 2;
        const float* p = qkv + ((size_t)(bc*NSEQ + qt*64 + q))*HID + h*DHEAD + d4;
        float4 v = *(const float4*)p;
        Qs[q][d4]=v.x; Qs[q][d4+1]=v.y; Qs[q][d4+2]=v.z; Qs[q][d4+3]=v.w;
    }
    if (t < 64) { m_run[t] = -1e30f; l_run[t] = 0.f; }
    float o[8];
#pragma unroll
    for (int i=0;i<8;i++) o[i]=0.f;
    __syncthreads();

    for (int kt=0; kt<NSEQ/64; kt++) {
        // load K,V tiles
#pragma unroll
        for (int r=0;r<2;r++) {
            int f = t + r*256;
            int k = f >> 3, d4 = (f & 7) << 2;
            const float* base = qkv + ((size_t)(bc*NSEQ + kt*64 + k))*HID + h*DHEAD + d4;
            float4 kv = *(const float4*)(base + DMODEL);
            Ks[k][d4]=kv.x; Ks[k][d4+1]=kv.y; Ks[k][d4+2]=kv.z; Ks[k][d4+3]=kv.w;
            float4 vv = *(const float4*)(base + 2*DMODEL);
            Vs[k][d4]=vv.x; Vs[k][d4+1]=vv.y; Vs[k][d4+2]=vv.z; Vs[k][d4+3]=vv.w;
        }
        __syncthreads();
        // QK^T : thread -> kv column k = t&63, query group qg = t>>6 (16 queries)
        {
            int k  = t & 63;
            int qg = t >> 6;
            float kreg[32];
#pragma unroll
            for (int d=0;d<32;d++) kreg[d] = Ks[k][d];
#pragma unroll
            for (int qi=0; qi<16; qi++) {
                int q = qg*16 + qi;
                float s = 0.f;
#pragma unroll
                for (int d=0;d<32;d++) s += Qs[q][d]*kreg[d];
                Ss[q][k] = s * scale;
            }
        }
        __syncthreads();
        // online softmax: warp owns 8 rows
#pragma unroll
        for (int i=0;i<8;i++) {
            int q = warp*8 + i;
            float s0 = Ss[q][lane], s1 = Ss[q][lane+32];
            float mx = fmaxf(s0, s1);
#pragma unroll
            for (int off=16; off; off>>=1) mx = fmaxf(mx, __shfl_xor_sync(0xffffffffu, mx, off));
            float mold = m_run[q];
            float mnew = fmaxf(mold, mx);
            float al = __expf(mold - mnew);
            float p0 = __expf(s0 - mnew), p1 = __expf(s1 - mnew);
            Ss[q][lane] = p0; Ss[q][lane+32] = p1;
            float ps = p0 + p1;
#pragma unroll
            for (int off=16; off; off>>=1) ps += __shfl_xor_sync(0xffffffffu, ps, off);
            if (lane==0) { m_run[q]=mnew; l_run[q]=l_run[q]*al + ps; alpha_s[q]=al; }
        }
        __syncthreads();
        // P @ V : warp owns rows warp*8..+7, lane = d
#pragma unroll
        for (int i=0;i<8;i++) o[i] *= alpha_s[warp*8+i];
#pragma unroll 4
        for (int k=0;k<64;k++) {
            float vv = Vs[k][lane];
#pragma unroll
            for (int i=0;i<8;i++) o[i] += Ss[warp*8+i][k]*vv;
        }
        __syncthreads();
    }
#pragma unroll
    for (int i=0;i<8;i++) {
        int q = warp*8 + i;
        out[((size_t)(bc*NSEQ + qt*64 + q))*DMODEL + h*DHEAD + lane] = o[i] / l_run[q];
    }
}

// ---------------- swiglu combine: t1 = silu(t1)*t3 ----------------
__global__ __launch_bounds__(256) void swiglu_kernel(
    float* __restrict__ t1, const float* __restrict__ t3, int n4)
{
    int i = blockIdx.x*256 + threadIdx.x;
    if (i >= n4) return;
    float4 a = ((const float4*)t1)[i];
    float4 b = ((const float4*)t3)[i];
    a.x = a.x / (1.f + __expf(-a.x)) * b.x;
    a.y = a.y / (1.f + __expf(-a.y)) * b.y;
    a.z = a.z / (1.f + __expf(-a.z)) * b.z;
    a.w = a.w / (1.f + __expf(-a.w)) * b.w;
    ((float4*)t1)[i] = a;
}

// ---------------- edge bucketing (single block, deterministic) ----------------
// data_to_logical is [2, E] of either int32 or int64 (jax x64 ambiguity).
// Detect int64 by zero high-words at odd int32 positions of the src row.
__global__ void bucket_kernel(const int* __restrict__ w)
{
    __shared__ int s_is64;
    __shared__ int s_cnt[LLOG];
    __shared__ int s_st[LLOG+1];
    int t = threadIdx.x;
    if (t == 0) {
        int z = 0;
        for (int i=1;i<64;i+=2) z |= w[i];
        s_is64 = (z == 0);
    }
    __syncthreads();
    int is64 = s_is64;
    int cnt = 0;
    for (int e=0;e<NEDGE;e++) {
        int dst = is64 ? w[2*NEDGE + 2*e] : w[NEDGE + e];
        cnt += (dst == t);
    }
    s_cnt[t] = cnt;
    __syncthreads();
    if (t == 0) {
        int acc = 0;
        for (int l=0;l<LLOG;l++) { s_st[l] = acc; acc += s_cnt[l]; }
        s_st[LLOG] = acc;
    }
    __syncthreads();
    g_start[t] = s_st[t];
    if (t == 0) g_start[LLOG] = s_st[LLOG];
    int idx = s_st[t];
    for (int e=0;e<NEDGE;e++) {
        int dst = is64 ? w[2*NEDGE + 2*e] : w[NEDGE + e];
        if (dst == t) {
            int src = is64 ? w[2*e] : w[e];
            g_order[idx++] = src;
        }
    }
}

// ---------------- scatter-multiply: l[bc,l,d] = prod over edges ----------------
__global__ __launch_bounds__(256) void scatterprod_kernel(
    const float* __restrict__ x3, float* __restrict__ lout)
{
    int l = blockIdx.x, bc = blockIdx.y, d = threadIdx.x;
    int s = g_start[l], e = g_start[l+1];
    float p = 1.f;
    const float* base = x3 + (size_t)bc*NSEQ*DMODEL + d;
    for (int i=s; i<e; i++) p *= base[(size_t)g_order[i]*DMODEL];
    lout[((size_t)bc*LLOG + l)*DMODEL + d] = p;
}

// ---------------- head: out[t] = dot(l2[t], head_w) + head_b ----------------
__global__ __launch_bounds__(256) void head_kernel(
    const float* __restrict__ l2, const float* __restrict__ hw,
    const float* __restrict__ hb, float* __restrict__ out)
{
    int tok  = blockIdx.x*8 + (threadIdx.x >> 5);
    int lane = threadIdx.x & 31;
    const float* p = l2 + (size_t)tok*DMODEL;
    float s = 0.f;
#pragma unroll
    for (int i=0;i<8;i++) s += p[lane + 32*i]*hw[lane + 32*i];
#pragma unroll
    for (int off=16; off; off>>=1) s += __shfl_xor_sync(0xffffffffu, s, off);
    if (lane == 0) out[tok] = s + hb[0];
}

// ---------------- host orchestration ----------------
static inline void launch_gemm(int epi, const float* A, const float* W,
                               const float* bias, const float* resid,
                               float* C, int M, int Nn, int K)
{
    dim3 grid(Nn/GBN, M/GBM);
    if      (epi == 0) gemm_kernel<0><<<grid,256>>>(A,W,bias,resid,C,M,Nn,K);
    else if (epi == 1) gemm_kernel<1><<<grid,256>>>(A,W,bias,resid,C,M,Nn,K);
    else               gemm_kernel<2><<<grid,256>>>(A,W,bias,resid,C,M,Nn,K);
}

extern "C" void kernel_launch(void* const* d_in, const int* in_sizes, int n_in,
                              void* d_out, int out_size)
{
    (void)in_sizes; (void)n_in; (void)out_size;
    const float* v           = (const float*)d_in[0];
    const int*   d2l         = (const int*)  d_in[1];
    const float* attn_norm_w = (const float*)d_in[2];
    const float* in_proj_w   = (const float*)d_in[3];
    const float* in_proj_b   = (const float*)d_in[4];
    const float* out_w       = (const float*)d_in[5];
    const float* out_b       = (const float*)d_in[6];
    const float* ffn_norm_w  = (const float*)d_in[7];
    const float* ffn_w1      = (const float*)d_in[8];
    const float* ffn_w2      = (const float*)d_in[9];
    const float* ffn_w3      = (const float*)d_in[10];
    const float* du_norm_w   = (const float*)d_in[11];
    const float* du_w1       = (const float*)d_in[12];
    const float* du_w2       = (const float*)d_in[13];
    const float* du_w3       = (const float*)d_in[14];
    const float* lu_norm_w   = (const float*)d_in[15];
    const float* lu_w1       = (const float*)d_in[16];
    const float* lu_w2       = (const float*)d_in[17];
    const float* lu_w3       = (const float*)d_in[18];
    const float* head_w      = (const float*)d_in[19];
    const float* head_b      = (const float*)d_in[20];
    float* out = (float*)d_out;

    float *buf1, *buf2, *xn, *a, *x2, *x3, *lb, *l2;
    cudaGetSymbolAddress((void**)&buf1, g_buf1);
    cudaGetSymbolAddress((void**)&buf2, g_buf2);
    cudaGetSymbolAddress((void**)&xn,   g_xn);
    cudaGetSymbolAddress((void**)&a,    g_a);
    cudaGetSymbolAddress((void**)&x2,   g_x2);
    cudaGetSymbolAddress((void**)&x3,   g_x3);
    cudaGetSymbolAddress((void**)&lb,   g_l);
    cudaGetSymbolAddress((void**)&l2,   g_l2);

    // 1) attn pre-norm
    rms_kernel<<<NTOK/8,256>>>(v, attn_norm_w, xn);
    // 2) qkv projection (+bias)
    launch_gemm(0, xn, in_proj_w, in_proj_b, nullptr, buf1, NTOK, 3*DMODEL, DMODEL);
    // 3) flash attention -> buf2 (first NTOK*DMODEL floats)
    { dim3 g(NSEQ/64, NHEAD, BC); attn_kernel<<<g,256>>>(buf1, buf2); }
    // 4) out projection + bias + residual(x=v) -> a
    launch_gemm(1, buf2, out_w, out_b, v, a, NTOK, DMODEL, DMODEL);
    // 5) FFN
    rms_kernel<<<NTOK/8,256>>>(a, ffn_norm_w, xn);
    launch_gemm(0, xn, ffn_w1, nullptr, nullptr, buf1, NTOK, HID, DMODEL);
    launch_gemm(0, xn, ffn_w3, nullptr, nullptr, buf2, NTOK, HID, DMODEL);
    swiglu_kernel<<<(NTOK*HID/4+255)/256,256>>>(buf1, buf2, NTOK*HID/4);
    launch_gemm(1, buf1, ffn_w2, nullptr, a, x2, NTOK, DMODEL, HID);
    // 6) du block with tanh(... + x2)
    rms_kernel<<<NTOK/8,256>>>(x2, du_norm_w, xn);
    launch_gemm(0, xn, du_w1, nullptr, nullptr, buf1, NTOK, HID, DMODEL);
    launch_gemm(0, xn, du_w3, nullptr, nullptr, buf2, NTOK, HID, DMODEL);
    swiglu_kernel<<<(NTOK*HID/4+255)/256,256>>>(buf1, buf2, NTOK*HID/4);
    launch_gemm(2, buf1, du_w2, nullptr, x2, x3, NTOK, DMODEL, HID);
    // 7) scatter-multiply into l
    bucket_kernel<<<1,256>>>(d2l);
    { dim3 g(LLOG, BC); scatterprod_kernel<<<g,256>>>(x3, lb); }
    // 8) lu block
    rms_kernel<<<NTOKL/8,256>>>(lb, lu_norm_w, xn);
    launch_gemm(0, xn, lu_w1, nullptr, nullptr, buf1, NTOKL, HID, DMODEL);
    launch_gemm(0, xn, lu_w3, nullptr, nullptr, buf2, NTOKL, HID, DMODEL);
    swiglu_kernel<<<(NTOKL*HID/4+255)/256,256>>>(buf1, buf2, NTOKL*HID/4);
    launch_gemm(1, buf1, lu_w2, nullptr, lb, l2, NTOKL, DMODEL, HID);
    // 9) head
    head_kernel<<<NTOKL/8,256>>>(l2, head_w, head_b, out);
}

// round 5
// speedup vs baseline: 1.4307x; 1.4307x over previous
#include <cuda_runtime.h>
#include <cuda_bf16.h>
#include <math.h>
#include <stdint.h>

// ---------------- problem constants ----------------
#define BC    32          // B*C
#define NSEQ  1024
#define DMODEL 256
#define NHEAD 8
#define DHEAD 32
#define HID   768
#define NEDGE 8192
#define LLOG  256
#define NTOK  (BC*NSEQ)   // 32768
#define NTOKL (BC*LLOG)   // 8192

// ---------------- scratch (__device__ globals; no allocs) ----------------
__device__ float g_buf1[NTOK*HID];   // qkv / t1
__device__ float g_buf2[NTOK*HID];   // t3 ; attn_out lives in first NTOK*DMODEL
__device__ float g_xn  [NTOK*DMODEL];
__device__ float g_a   [NTOK*DMODEL];
__device__ float g_x2  [NTOK*DMODEL];
__device__ float g_x3  [NTOK*DMODEL];
__device__ float g_l   [NTOKL*DMODEL];
__device__ float g_l2  [NTOKL*DMODEL];
__device__ int   g_start[LLOG+1];
__device__ int   g_order[NEDGE];

// ================= mma.sync helpers (generic PTX, works on compute_103) ====
__device__ __forceinline__ uint32_t smem_u32(const void* p) {
    uint32_t a;
    asm("{ .reg .u64 t; cvta.to.shared.u64 t, %1; cvt.u32.u64 %0, t; }"
        : "=r"(a) : "l"(p));
    return a;
}
__device__ __forceinline__ void ldsm4(uint32_t addr, uint32_t& r0, uint32_t& r1,
                                      uint32_t& r2, uint32_t& r3) {
    asm volatile("ldmatrix.sync.aligned.m8n8.x4.shared.b16 {%0,%1,%2,%3}, [%4];"
                 : "=r"(r0), "=r"(r1), "=r"(r2), "=r"(r3) : "r"(addr));
}
__device__ __forceinline__ void mma16816(float* d, uint32_t a0, uint32_t a1,
                                         uint32_t a2, uint32_t a3,
                                         uint32_t b0, uint32_t b1) {
    asm volatile(
        "mma.sync.aligned.m16n8k16.row.col.f32.bf16.bf16.f32 "
        "{%0,%1,%2,%3}, {%4,%5,%6,%7}, {%8,%9}, {%0,%1,%2,%3};"
        : "+f"(d[0]), "+f"(d[1]), "+f"(d[2]), "+f"(d[3])
        : "r"(a0), "r"(a1), "r"(a2), "r"(a3), "r"(b0), "r"(b1));
}
__device__ __forceinline__ uint32_t packbf(float x, float y) {
    __nv_bfloat162 h = __floats2bfloat162_rn(x, y);
    return *(uint32_t*)&h;
}

// ---------------- tensor-core GEMM: C[M,N] = A[M,K] @ W[N,K]^T (+epi) ------
// CTA 128x128, BK=32, 512 threads (16 warps, 4x4 of 32x32 warp tiles).
// bf16 hi/lo split, 3-term compensation. Double-buffered SMEM.
// EPI: 0 = (+bias), 1 = (+bias)+resid, 2 = tanh((+bias)+resid)
#define GS 40                 // smem row stride in bf16 elements (32 + 8 pad)
#define ARR (128*GS)          // 5120 elements per array
#define BUFE (4*ARR)          // elements per buffer (Ahi,Alo,Bhi,Blo)
#define MG_SMEM (2*BUFE*2)    // bytes = 81920

template<int EPI>
__global__ __launch_bounds__(512) void mgemm_kernel(
    const float* __restrict__ A, const float* __restrict__ W,
    const float* __restrict__ bias, const float* __restrict__ resid,
    float* __restrict__ C, int M, int Nn, int K)
{
    extern __shared__ __nv_bfloat16 sm[];
    const int t    = threadIdx.x;
    const int lane = t & 31;
    const int wid  = t >> 5;
    const int wm   = wid >> 2;           // 0..3 : warp row   (32 rows)
    const int wn   = wid & 3;            // 0..3 : warp col   (32 cols)
    const int bm   = blockIdx.y * 128;
    const int bn   = blockIdx.x * 128;

    const int lrow = t >> 2;             // 0..127  (loader row)
    const int lcol = (t & 3) * 8;        // 0,8,16,24

    float acc[2][4][4];
#pragma unroll
    for (int i=0;i<2;i++)
#pragma unroll
        for (int j=0;j<4;j++)
#pragma unroll
            for (int e=0;e<4;e++) acc[i][j][e]=0.f;

    const uint32_t sbase = smem_u32(sm);
    const int nc = K / 32;

    // ---- prologue: load + convert + store chunk 0 ----
    {
        const float* pa = A + (size_t)(bm + lrow)*K + lcol;
        const float* pb = W + (size_t)(bn + lrow)*K + lcol;
        float4 va0 = *(const float4*)pa, va1 = *(const float4*)(pa+4);
        float4 vb0 = *(const float4*)pb, vb1 = *(const float4*)(pb+4);
        float fa[8] = {va0.x,va0.y,va0.z,va0.w,va1.x,va1.y,va1.z,va1.w};
        float fb[8] = {vb0.x,vb0.y,vb0.z,vb0.w,vb1.x,vb1.y,vb1.z,vb1.w};
        uint32_t ah[4], al[4], bh[4], bl[4];
#pragma unroll
        for (int j=0;j<4;j++) {
            float x0=fa[2*j], x1=fa[2*j+1];
            float h0=__bfloat162float(__float2bfloat16_rn(x0));
            float h1=__bfloat162float(__float2bfloat16_rn(x1));
            ah[j]=packbf(h0,h1); al[j]=packbf(x0-h0,x1-h1);
            float y0=fb[2*j], y1=fb[2*j+1];
            float g0=__bfloat162float(__float2bfloat16_rn(y0));
            float g1=__bfloat162float(__float2bfloat16_rn(y1));
            bh[j]=packbf(g0,g1); bl[j]=packbf(y0-g0,y1-g1);
        }
        int off = lrow*GS + lcol;
        *(uint4*)&sm[0*ARR + off] = make_uint4(ah[0],ah[1],ah[2],ah[3]);
        *(uint4*)&sm[1*ARR + off] = make_uint4(al[0],al[1],al[2],al[3]);
        *(uint4*)&sm[2*ARR + off] = make_uint4(bh[0],bh[1],bh[2],bh[3]);
        *(uint4*)&sm[3*ARR + off] = make_uint4(bl[0],bl[1],bl[2],bl[3]);
    }
    __syncthreads();

    for (int c = 0; c < nc; c++) {
        // ---- issue gmem loads for next chunk ----
        float4 va0, va1, vb0, vb1;
        if (c + 1 < nc) {
            const float* pa = A + (size_t)(bm + lrow)*K + (c+1)*32 + lcol;
            const float* pb = W + (size_t)(bn + lrow)*K + (c+1)*32 + lcol;
            va0 = *(const float4*)pa; va1 = *(const float4*)(pa+4);
            vb0 = *(const float4*)pb; vb1 = *(const float4*)(pb+4);
        }

        // ---- MMA on current buffer ----
        uint32_t base = sbase + (uint32_t)(c & 1) * (BUFE*2);
#pragma unroll
        for (int ks = 0; ks < 2; ks++) {
            uint32_t ahf[2][4], alf[2][4], bhf[2][4], blf[2][4];
            int rl = lane & 15, ch = (lane >> 4) * 8;
            int col = ks*16 + ch;
#pragma unroll
            for (int mt=0; mt<2; mt++) {
                int row = wm*32 + mt*16 + rl;
                uint32_t o = (uint32_t)(row*GS + col)*2;
                ldsm4(base + 0*ARR*2 + o, ahf[mt][0],ahf[mt][1],ahf[mt][2],ahf[mt][3]);
                ldsm4(base + 1*ARR*2 + o, alf[mt][0],alf[mt][1],alf[mt][2],alf[mt][3]);
            }
#pragma unroll
            for (int g=0; g<2; g++) {
                int row = wn*32 + g*16 + rl;
                uint32_t o = (uint32_t)(row*GS + col)*2;
                ldsm4(base + 2*ARR*2 + o, bhf[g][0],bhf[g][1],bhf[g][2],bhf[g][3]);
                ldsm4(base + 3*ARR*2 + o, blf[g][0],blf[g][1],blf[g][2],blf[g][3]);
            }
#pragma unroll
            for (int mt=0; mt<2; mt++)
#pragma unroll
                for (int g=0; g<2; g++)
#pragma unroll
                    for (int sub=0; sub<2; sub++) {
                        int nt = g*2 + sub;
                        uint32_t h0 = sub ? bhf[g][1] : bhf[g][0];
                        uint32_t h1 = sub ? bhf[g][3] : bhf[g][2];
                        uint32_t l0 = sub ? blf[g][1] : blf[g][0];
                        uint32_t l1 = sub ? blf[g][3] : blf[g][2];
                        mma16816(acc[mt][nt], ahf[mt][0],ahf[mt][1],ahf[mt][2],ahf[mt][3], h0,h1);
                        mma16816(acc[mt][nt], ahf[mt][0],ahf[mt][1],ahf[mt][2],ahf[mt][3], l0,l1);
                        mma16816(acc[mt][nt], alf[mt][0],alf[mt][1],alf[mt][2],alf[mt][3], h0,h1);
                    }
        }

        // ---- convert + store next chunk into other buffer ----
        if (c + 1 < nc) {
            float fa[8] = {va0.x,va0.y,va0.z,va0.w,va1.x,va1.y,va1.z,va1.w};
            float fb[8] = {vb0.x,vb0.y,vb0.z,vb0.w,vb1.x,vb1.y,vb1.z,vb1.w};
            uint32_t ah[4], al[4], bh[4], bl[4];
#pragma unroll
            for (int j=0;j<4;j++) {
                float x0=fa[2*j], x1=fa[2*j+1];
                float h0=__bfloat162float(__float2bfloat16_rn(x0));
                float h1=__bfloat162float(__float2bfloat16_rn(x1));
                ah[j]=packbf(h0,h1); al[j]=packbf(x0-h0,x1-h1);
                float y0=fb[2*j], y1=fb[2*j+1];
                float g0=__bfloat162float(__float2bfloat16_rn(y0));
                float g1=__bfloat162float(__float2bfloat16_rn(y1));
                bh[j]=packbf(g0,g1); bl[j]=packbf(y0-g0,y1-g1);
            }
            __nv_bfloat16* dst = sm + ((c+1) & 1) * BUFE;
            int off = lrow*GS + lcol;
            *(uint4*)&dst[0*ARR + off] = make_uint4(ah[0],ah[1],ah[2],ah[3]);
            *(uint4*)&dst[1*ARR + off] = make_uint4(al[0],al[1],al[2],al[3]);
            *(uint4*)&dst[2*ARR + off] = make_uint4(bh[0],bh[1],bh[2],bh[3]);
            *(uint4*)&dst[3*ARR + off] = make_uint4(bl[0],bl[1],bl[2],bl[3]);
        }
        __syncthreads();
    }

    // ---- epilogue: D fragment -> gmem (float2 stores) ----
#pragma unroll
    for (int mt=0; mt<2; mt++)
#pragma unroll
        for (int nt=0; nt<4; nt++) {
            int m0 = bm + wm*32 + mt*16 + (lane >> 2);
            int n0 = bn + wn*32 + nt*8 + (lane & 3)*2;
            float2 bb = make_float2(0.f, 0.f);
            if (bias) bb = *(const float2*)(bias + n0);
            float v[4] = {acc[mt][nt][0]+bb.x, acc[mt][nt][1]+bb.y,
                          acc[mt][nt][2]+bb.x, acc[mt][nt][3]+bb.y};
            size_t i0 = (size_t)m0*Nn + n0;
            size_t i1 = (size_t)(m0+8)*Nn + n0;
            if (EPI >= 1) {
                float2 r0 = *(const float2*)(resid + i0);
                float2 r1 = *(const float2*)(resid + i1);
                v[0]+=r0.x; v[1]+=r0.y; v[2]+=r1.x; v[3]+=r1.y;
            }
            if (EPI == 2) {
                v[0]=tanhf(v[0]); v[1]=tanhf(v[1]);
                v[2]=tanhf(v[2]); v[3]=tanhf(v[3]);
            }
            *(float2*)(C + i0) = make_float2(v[0], v[1]);
            *(float2*)(C + i1) = make_float2(v[2], v[3]);
        }
}

// ---------------- RMS norm: warp per token ----------------
__global__ __launch_bounds__(256) void rms_kernel(
    const float* __restrict__ x, const float* __restrict__ w,
    float* __restrict__ y)
{
    int tok  = blockIdx.x*8 + (threadIdx.x >> 5);
    int lane = threadIdx.x & 31;
    const float* xp = x + (size_t)tok*DMODEL;
    float4 a = *(const float4*)(xp + lane*4);
    float4 b = *(const float4*)(xp + 128 + lane*4);
    float ss = a.x*a.x + a.y*a.y + a.z*a.z + a.w*a.w
             + b.x*b.x + b.y*b.y + b.z*b.z + b.w*b.w;
#pragma unroll
    for (int off=16; off; off>>=1) ss += __shfl_xor_sync(0xffffffffu, ss, off);
    float r = rsqrtf(ss*(1.0f/DMODEL) + 1e-5f);
    float4 wa = *(const float4*)(w + lane*4);
    float4 wb = *(const float4*)(w + 128 + lane*4);
    float* yp = y + (size_t)tok*DMODEL;
    float4 oa = make_float4(a.x*r*wa.x, a.y*r*wa.y, a.z*r*wa.z, a.w*r*wa.w);
    float4 ob = make_float4(b.x*r*wb.x, b.y*r*wb.y, b.z*r*wb.z, b.w*r*wb.w);
    *(float4*)(yp + lane*4)       = oa;
    *(float4*)(yp + 128 + lane*4) = ob;
}

// ---------------- flash attention: fp32, 64q x 64kv tiles ----------------
__global__ __launch_bounds__(256) void attn_kernel(
    const float* __restrict__ qkv, float* __restrict__ out)
{
    int qt = blockIdx.x, h = blockIdx.y, bc = blockIdx.z;
    __shared__ float Qs[64][33];
    __shared__ float Ks[64][33];
    __shared__ float Vs[64][33];
    __shared__ float Ss[64][64];
    __shared__ float m_run[64], l_run[64], alpha_s[64];

    int t = threadIdx.x;
    int warp = t >> 5, lane = t & 31;
    const float scale = 0.17677669529663687f;  // 1/sqrt(32)

#pragma unroll
    for (int r=0;r<2;r++) {
        int f = t + r*256;
        int q = f >> 3, d4 = (f & 7) << 2;
        const float* p = qkv + ((size_t)(bc*NSEQ + qt*64 + q))*HID + h*DHEAD + d4;
        float4 v = *(const float4*)p;
        Qs[q][d4]=v.x; Qs[q][d4+1]=v.y; Qs[q][d4+2]=v.z; Qs[q][d4+3]=v.w;
    }
    if (t < 64) { m_run[t] = -1e30f; l_run[t] = 0.f; }
    float o[8];
#pragma unroll
    for (int i=0;i<8;i++) o[i]=0.f;
    __syncthreads();

    for (int kt=0; kt<NSEQ/64; kt++) {
#pragma unroll
        for (int r=0;r<2;r++) {
            int f = t + r*256;
            int k = f >> 3, d4 = (f & 7) << 2;
            const float* base = qkv + ((size_t)(bc*NSEQ + kt*64 + k))*HID + h*DHEAD + d4;
            float4 kv = *(const float4*)(base + DMODEL);
            Ks[k][d4]=kv.x; Ks[k][d4+1]=kv.y; Ks[k][d4+2]=kv.z; Ks[k][d4+3]=kv.w;
            float4 vv = *(const float4*)(base + 2*DMODEL);
            Vs[k][d4]=vv.x; Vs[k][d4+1]=vv.y; Vs[k][d4+2]=vv.z; Vs[k][d4+3]=vv.w;
        }
        __syncthreads();
        {
            int k  = t & 63;
            int qg = t >> 6;
            float kreg[32];
#pragma unroll
            for (int d=0;d<32;d++) kreg[d] = Ks[k][d];
#pragma unroll
            for (int qi=0; qi<16; qi++) {
                int q = qg*16 + qi;
                float s = 0.f;
#pragma unroll
                for (int d=0;d<32;d++) s += Qs[q][d]*kreg[d];
                Ss[q][k] = s * scale;
            }
        }
        __syncthreads();
#pragma unroll
        for (int i=0;i<8;i++) {
            int q = warp*8 + i;
            float s0 = Ss[q][lane], s1 = Ss[q][lane+32];
            float mx = fmaxf(s0, s1);
#pragma unroll
            for (int off=16; off; off>>=1) mx = fmaxf(mx, __shfl_xor_sync(0xffffffffu, mx, off));
            float mold = m_run[q];
            float mnew = fmaxf(mold, mx);
            float al = __expf(mold - mnew);
            float p0 = __expf(s0 - mnew), p1 = __expf(s1 - mnew);
            Ss[q][lane] = p0; Ss[q][lane+32] = p1;
            float ps = p0 + p1;
#pragma unroll
            for (int off=16; off; off>>=1) ps += __shfl_xor_sync(0xffffffffu, ps, off);
            if (lane==0) { m_run[q]=mnew; l_run[q]=l_run[q]*al + ps; alpha_s[q]=al; }
        }
        __syncthreads();
#pragma unroll
        for (int i=0;i<8;i++) o[i] *= alpha_s[warp*8+i];
#pragma unroll 4
        for (int k=0;k<64;k++) {
            float vv = Vs[k][lane];
#pragma unroll
            for (int i=0;i<8;i++) o[i] += Ss[warp*8+i][k]*vv;
        }
        __syncthreads();
    }
#pragma unroll
    for (int i=0;i<8;i++) {
        int q = warp*8 + i;
        out[((size_t)(bc*NSEQ + qt*64 + q))*DMODEL + h*DHEAD + lane] = o[i] / l_run[q];
    }
}

// ---------------- swiglu combine: t1 = silu(t1)*t3 ----------------
__global__ __launch_bounds__(256) void swiglu_kernel(
    float* __restrict__ t1, const float* __restrict__ t3, int n4)
{
    int i = blockIdx.x*256 + threadIdx.x;
    if (i >= n4) return;
    float4 a = ((const float4*)t1)[i];
    float4 b = ((const float4*)t3)[i];
    a.x = a.x / (1.f + __expf(-a.x)) * b.x;
    a.y = a.y / (1.f + __expf(-a.y)) * b.y;
    a.z = a.z / (1.f + __expf(-a.z)) * b.z;
    a.w = a.w / (1.f + __expf(-a.w)) * b.w;
    ((float4*)t1)[i] = a;
}

// ---------------- edge bucketing (single block, deterministic) -------------
__global__ void bucket_kernel(const int* __restrict__ w)
{
    __shared__ int s_is64;
    __shared__ int s_cnt[LLOG];
    __shared__ int s_st[LLOG+1];
    int t = threadIdx.x;
    if (t == 0) {
        int z = 0;
        for (int i=1;i<64;i+=2) z |= w[i];
        s_is64 = (z == 0);
    }
    __syncthreads();
    int is64 = s_is64;
    int cnt = 0;
    for (int e=0;e<NEDGE;e++) {
        int dst = is64 ? w[2*NEDGE + 2*e] : w[NEDGE + e];
        cnt += (dst == t);
    }
    s_cnt[t] = cnt;
    __syncthreads();
    if (t == 0) {
        int acc = 0;
        for (int l=0;l<LLOG;l++) { s_st[l] = acc; acc += s_cnt[l]; }
        s_st[LLOG] = acc;
    }
    __syncthreads();
    g_start[t] = s_st[t];
    if (t == 0) g_start[LLOG] = s_st[LLOG];
    int idx = s_st[t];
    for (int e=0;e<NEDGE;e++) {
        int dst = is64 ? w[2*NEDGE + 2*e] : w[NEDGE + e];
        if (dst == t) {
            int src = is64 ? w[2*e] : w[e];
            g_order[idx++] = src;
        }
    }
}

// ---------------- scatter-multiply ----------------
__global__ __launch_bounds__(256) void scatterprod_kernel(
    const float* __restrict__ x3, float* __restrict__ lout)
{
    int l = blockIdx.x, bc = blockIdx.y, d = threadIdx.x;
    int s = g_start[l], e = g_start[l+1];
    float p = 1.f;
    const float* base = x3 + (size_t)bc*NSEQ*DMODEL + d;
    for (int i=s; i<e; i++) p *= base[(size_t)g_order[i]*DMODEL];
    lout[((size_t)bc*LLOG + l)*DMODEL + d] = p;
}

// ---------------- head ----------------
__global__ __launch_bounds__(256) void head_kernel(
    const float* __restrict__ l2, const float* __restrict__ hw,
    const float* __restrict__ hb, float* __restrict__ out)
{
    int tok  = blockIdx.x*8 + (threadIdx.x >> 5);
    int lane = threadIdx.x & 31;
    const float* p = l2 + (size_t)tok*DMODEL;
    float s = 0.f;
#pragma unroll
    for (int i=0;i<8;i++) s += p[lane + 32*i]*hw[lane + 32*i];
#pragma unroll
    for (int off=16; off; off>>=1) s += __shfl_xor_sync(0xffffffffu, s, off);
    if (lane == 0) out[tok] = s + hb[0];
}

// ---------------- host orchestration ----------------
static inline void launch_mgemm(int epi, const float* A, const float* W,
                                const float* bias, const float* resid,
                                float* C, int M, int Nn, int K)
{
    dim3 grid(Nn/128, M/128);
    if (epi == 0) {
        cudaFuncSetAttribute(mgemm_kernel<0>, cudaFuncAttributeMaxDynamicSharedMemorySize, MG_SMEM);
        mgemm_kernel<0><<<grid,512,MG_SMEM>>>(A,W,bias,resid,C,M,Nn,K);
    } else if (epi == 1) {
        cudaFuncSetAttribute(mgemm_kernel<1>, cudaFuncAttributeMaxDynamicSharedMemorySize, MG_SMEM);
        mgemm_kernel<1><<<grid,512,MG_SMEM>>>(A,W,bias,resid,C,M,Nn,K);
    } else {
        cudaFuncSetAttribute(mgemm_kernel<2>, cudaFuncAttributeMaxDynamicSharedMemorySize, MG_SMEM);
        mgemm_kernel<2><<<grid,512,MG_SMEM>>>(A,W,bias,resid,C,M,Nn,K);
    }
}

extern "C" void kernel_launch(void* const* d_in, const int* in_sizes, int n_in,
                              void* d_out, int out_size)
{
    (void)in_sizes; (void)n_in; (void)out_size;
    const float* v           = (const float*)d_in[0];
    const int*   d2l         = (const int*)  d_in[1];
    const float* attn_norm_w = (const float*)d_in[2];
    const float* in_proj_w   = (const float*)d_in[3];
    const float* in_proj_b   = (const float*)d_in[4];
    const float* out_w       = (const float*)d_in[5];
    const float* out_b       = (const float*)d_in[6];
    const float* ffn_norm_w  = (const float*)d_in[7];
    const float* ffn_w1      = (const float*)d_in[8];
    const float* ffn_w2      = (const float*)d_in[9];
    const float* ffn_w3      = (const float*)d_in[10];
    const float* du_norm_w   = (const float*)d_in[11];
    const float* du_w1       = (const float*)d_in[12];
    const float* du_w2       = (const float*)d_in[13];
    const float* du_w3       = (const float*)d_in[14];
    const float* lu_norm_w   = (const float*)d_in[15];
    const float* lu_w1       = (const float*)d_in[16];
    const float* lu_w2       = (const float*)d_in[17];
    const float* lu_w3       = (const float*)d_in[18];
    const float* head_w      = (const float*)d_in[19];
    const float* head_b      = (const float*)d_in[20];
    float* out = (float*)d_out;

    float *buf1, *buf2, *xn, *a, *x2, *x3, *lb, *l2;
    cudaGetSymbolAddress((void**)&buf1, g_buf1);
    cudaGetSymbolAddress((void**)&buf2, g_buf2);
    cudaGetSymbolAddress((void**)&xn,   g_xn);
    cudaGetSymbolAddress((void**)&a,    g_a);
    cudaGetSymbolAddress((void**)&x2,   g_x2);
    cudaGetSymbolAddress((void**)&x3,   g_x3);
    cudaGetSymbolAddress((void**)&lb,   g_l);
    cudaGetSymbolAddress((void**)&l2,   g_l2);

    // 1) attn pre-norm
    rms_kernel<<<NTOK/8,256>>>(v, attn_norm_w, xn);
    // 2) qkv projection (+bias)
    launch_mgemm(0, xn, in_proj_w, in_proj_b, nullptr, buf1, NTOK, 3*DMODEL, DMODEL);
    // 3) flash attention -> buf2
    { dim3 g(NSEQ/64, NHEAD, BC); attn_kernel<<<g,256>>>(buf1, buf2); }
    // 4) out projection + bias + residual(x=v) -> a
    launch_mgemm(1, buf2, out_w, out_b, v, a, NTOK, DMODEL, DMODEL);
    // 5) FFN
    rms_kernel<<<NTOK/8,256>>>(a, ffn_norm_w, xn);
    launch_mgemm(0, xn, ffn_w1, nullptr, nullptr, buf1, NTOK, HID, DMODEL);
    launch_mgemm(0, xn, ffn_w3, nullptr, nullptr, buf2, NTOK, HID, DMODEL);
    swiglu_kernel<<<(NTOK*HID/4+255)/256,256>>>(buf1, buf2, NTOK*HID/4);
    launch_mgemm(1, buf1, ffn_w2, nullptr, a, x2, NTOK, DMODEL, HID);
    // 6) du block with tanh(... + x2)
    rms_kernel<<<NTOK/8,256>>>(x2, du_norm_w, xn);
    launch_mgemm(0, xn, du_w1, nullptr, nullptr, buf1, NTOK, HID, DMODEL);
    launch_mgemm(0, xn, du_w3, nullptr, nullptr, buf2, NTOK, HID, DMODEL);
    swiglu_kernel<<<(NTOK*HID/4+255)/256,256>>>(buf1, buf2, NTOK*HID/4);
    launch_mgemm(2, buf1, du_w2, nullptr, x2, x3, NTOK, DMODEL, HID);
    // 7) scatter-multiply into l
    bucket_kernel<<<1,256>>>(d2l);
    { dim3 g(LLOG, BC); scatterprod_kernel<<<g,256>>>(x3, lb); }
    // 8) lu block
    rms_kernel<<<NTOKL/8,256>>>(lb, lu_norm_w, xn);
    launch_mgemm(0, xn, lu_w1, nullptr, nullptr, buf1, NTOKL, HID, DMODEL);
    launch_mgemm(0, xn, lu_w3, nullptr, nullptr, buf2, NTOKL, HID, DMODEL);
    swiglu_kernel<<<(NTOKL*HID/4+255)/256,256>>>(buf1, buf2, NTOKL*HID/4);
    launch_mgemm(1, buf1, lu_w2, nullptr, lb, l2, NTOKL, DMODEL, HID);
    // 9) head
    head_kernel<<<NTOKL/8,256>>>(l2, head_w, head_b, out);
}

// round 7
// speedup vs baseline: 2.0722x; 1.4484x over previous
#include <cuda_runtime.h>
#include <cuda_bf16.h>
#include <math.h>
#include <stdint.h>

// ---------------- problem constants ----------------
#define BC    32
#define NSEQ  1024
#define DMODEL 256
#define NHEAD 8
#define DHEAD 32
#define HID   768
#define NEDGE 8192
#define LLOG  256
#define NTOK  (BC*NSEQ)   // 32768
#define NTOKL (BC*LLOG)   // 8192
#define WTOT  2031616     // total weight elements

// ---------------- scratch (__device__ globals; no allocs) ----------------
__device__ float g_buf1[NTOK*HID];      // t1 fp32 (w1 out)
__device__ float g_buf2[NTOK*HID];      // t3 fp32 (w3 out)
__device__ float g_a   [NTOK*DMODEL];
__device__ float g_x2  [NTOK*DMODEL];
__device__ float g_x3  [NTOK*DMODEL];
__device__ float g_l   [NTOKL*DMODEL];
__device__ float g_l2  [NTOKL*DMODEL];
__device__ int   g_start[LLOG+1];
__device__ int   g_order[NEDGE];
// bf16 hi/lo activations
__device__ __nv_bfloat16 g_xnh[NTOK*DMODEL], g_xnl[NTOK*DMODEL];
__device__ __nv_bfloat16 g_qkvh[NTOK*HID],  g_qkvl[NTOK*HID];
__device__ __nv_bfloat16 g_t1h[NTOK*HID],   g_t1l[NTOK*HID];
__device__ __nv_bfloat16 g_aoh[NTOK*DMODEL], g_aol[NTOK*DMODEL];
// bf16 hi/lo weights
__device__ __nv_bfloat16 g_whi[WTOT], g_wlo[WTOT];

// ================= mma helpers =================
__device__ __forceinline__ uint32_t smem_u32(const void* p) {
    uint32_t a;
    asm("{ .reg .u64 t; cvta.to.shared.u64 t, %1; cvt.u32.u64 %0, t; }"
        : "=r"(a) : "l"(p));
    return a;
}
__device__ __forceinline__ void ldsm4(uint32_t addr, uint32_t& r0, uint32_t& r1,
                                      uint32_t& r2, uint32_t& r3) {
    asm volatile("ldmatrix.sync.aligned.m8n8.x4.shared.b16 {%0,%1,%2,%3}, [%4];"
                 : "=r"(r0), "=r"(r1), "=r"(r2), "=r"(r3) : "r"(addr));
}
__device__ __forceinline__ void ldsm4t(uint32_t addr, uint32_t& r0, uint32_t& r1,
                                       uint32_t& r2, uint32_t& r3) {
    asm volatile("ldmatrix.sync.aligned.m8n8.x4.trans.shared.b16 {%0,%1,%2,%3}, [%4];"
                 : "=r"(r0), "=r"(r1), "=r"(r2), "=r"(r3) : "r"(addr));
}
__device__ __forceinline__ void mma16816(float* d, uint32_t a0, uint32_t a1,
                                         uint32_t a2, uint32_t a3,
                                         uint32_t b0, uint32_t b1) {
    asm volatile(
        "mma.sync.aligned.m16n8k16.row.col.f32.bf16.bf16.f32 "
        "{%0,%1,%2,%3}, {%4,%5,%6,%7}, {%8,%9}, {%0,%1,%2,%3};"
        : "+f"(d[0]), "+f"(d[1]), "+f"(d[2]), "+f"(d[3])
        : "r"(a0), "r"(a1), "r"(a2), "r"(a3), "r"(b0), "r"(b1));
}
__device__ __forceinline__ uint32_t packbf(float x, float y) {
    __nv_bfloat162 h = __floats2bfloat162_rn(x, y);
    return *(uint32_t*)&h;
}
__device__ __forceinline__ void cpasync16(uint32_t saddr, const void* g) {
    asm volatile("cp.async.cg.shared.global [%0], [%1], 16;" :: "r"(saddr), "l"(g));
}
__device__ __forceinline__ void cpcommit() {
    asm volatile("cp.async.commit_group;");
}

// ---------------- weight split kernel ----------------
__global__ __launch_bounds__(256) void wconv_kernel(
    const float* __restrict__ src, __nv_bfloat16* __restrict__ dh,
    __nv_bfloat16* __restrict__ dl, int n4)
{
    int i = blockIdx.x*256 + threadIdx.x;
    if (i >= n4) return;
    float4 v = ((const float4*)src)[i];
    float h0=__bfloat162float(__float2bfloat16_rn(v.x));
    float h1=__bfloat162float(__float2bfloat16_rn(v.y));
    float h2=__bfloat162float(__float2bfloat16_rn(v.z));
    float h3=__bfloat162float(__float2bfloat16_rn(v.w));
    ((uint2*)dh)[i] = make_uint2(packbf(h0,h1), packbf(h2,h3));
    ((uint2*)dl)[i] = make_uint2(packbf(v.x-h0,v.y-h1), packbf(v.z-h2,v.w-h3));
}

// ---------------- bf16 GEMM: C[M,N] = (Ah+Al)(Wh+Wl)^T 3-term ----------
// CTA 128x128, BK=32, 512 threads, cp.async double-buffered.
// EPI: 0 fp32(+bias); 1 fp32(+bias+resid); 2 fp32 tanh(+bias+resid); 3 bf16 hi/lo (+bias)
#define BGS 40
#define BARR (128*BGS)
#define BBUFE (4*BARR)
#define BG_SMEM (2*BBUFE*2)

template<int EPI>
__global__ __launch_bounds__(512) void bgemm_kernel(
    const __nv_bfloat16* __restrict__ Ah, const __nv_bfloat16* __restrict__ Al,
    const __nv_bfloat16* __restrict__ Wh, const __nv_bfloat16* __restrict__ Wl,
    const float* __restrict__ bias, const float* __restrict__ resid,
    float* __restrict__ C, __nv_bfloat16* __restrict__ Ch,
    __nv_bfloat16* __restrict__ Cl, int M, int Nn, int K)
{
    extern __shared__ __nv_bfloat16 sm[];
    const int t = threadIdx.x, lane = t & 31, wid = t >> 5;
    const int wm = wid >> 2, wn = wid & 3;
    const int bm = blockIdx.y * 128, bn = blockIdx.x * 128;
    const int lrow = t >> 2, lcol = (t & 3) * 8;
    const uint32_t sbase = smem_u32(sm);
    const int nc = K / 32;

    float acc[2][4][4];
#pragma unroll
    for (int i=0;i<2;i++)
#pragma unroll
        for (int j=0;j<4;j++)
#pragma unroll
            for (int e=0;e<4;e++) acc[i][j][e]=0.f;

    auto issue = [&](int c) {
        uint32_t soff = sbase + (uint32_t)(c & 1)*(BBUFE*2) + (uint32_t)(lrow*BGS + lcol)*2;
        size_t ga = (size_t)(bm + lrow)*K + c*32 + lcol;
        size_t gw = (size_t)(bn + lrow)*K + c*32 + lcol;
        cpasync16(soff + 0*BARR*2, Ah + ga);
        cpasync16(soff + 1*BARR*2, Al + ga);
        cpasync16(soff + 2*BARR*2, Wh + gw);
        cpasync16(soff + 3*BARR*2, Wl + gw);
        cpcommit();
    };
    issue(0);

    for (int c = 0; c < nc; c++) {
        if (c + 1 < nc) {
            issue(c + 1);
            asm volatile("cp.async.wait_group 1;");
        } else {
            asm volatile("cp.async.wait_group 0;");
        }
        __syncthreads();
        uint32_t base = sbase + (uint32_t)(c & 1)*(BBUFE*2);
#pragma unroll
        for (int ks = 0; ks < 2; ks++) {
            uint32_t ahf[2][4], alf[2][4], bhf[2][4], blf[2][4];
            int rl = lane & 15, ch = (lane >> 4) * 8;
            int col = ks*16 + ch;
#pragma unroll
            for (int mt=0; mt<2; mt++) {
                int row = wm*32 + mt*16 + rl;
                uint32_t o = (uint32_t)(row*BGS + col)*2;
                ldsm4(base + 0*BARR*2 + o, ahf[mt][0],ahf[mt][1],ahf[mt][2],ahf[mt][3]);
                ldsm4(base + 1*BARR*2 + o, alf[mt][0],alf[mt][1],alf[mt][2],alf[mt][3]);
            }
#pragma unroll
            for (int g=0; g<2; g++) {
                int row = wn*32 + g*16 + rl;
                uint32_t o = (uint32_t)(row*BGS + col)*2;
                ldsm4(base + 2*BARR*2 + o, bhf[g][0],bhf[g][1],bhf[g][2],bhf[g][3]);
                ldsm4(base + 3*BARR*2 + o, blf[g][0],blf[g][1],blf[g][2],blf[g][3]);
            }
#pragma unroll
            for (int mt=0; mt<2; mt++)
#pragma unroll
                for (int g=0; g<2; g++)
#pragma unroll
                    for (int sub=0; sub<2; sub++) {
                        int nt = g*2 + sub;
                        uint32_t h0 = sub ? bhf[g][1] : bhf[g][0];
                        uint32_t h1 = sub ? bhf[g][3] : bhf[g][2];
                        uint32_t l0 = sub ? blf[g][1] : blf[g][0];
                        uint32_t l1 = sub ? blf[g][3] : blf[g][2];
                        mma16816(acc[mt][nt], ahf[mt][0],ahf[mt][1],ahf[mt][2],ahf[mt][3], h0,h1);
                        mma16816(acc[mt][nt], ahf[mt][0],ahf[mt][1],ahf[mt][2],ahf[mt][3], l0,l1);
                        mma16816(acc[mt][nt], alf[mt][0],alf[mt][1],alf[mt][2],alf[mt][3], h0,h1);
                    }
        }
        __syncthreads();
    }

    // epilogue
#pragma unroll
    for (int mt=0; mt<2; mt++)
#pragma unroll
        for (int nt=0; nt<4; nt++) {
            int m0 = bm + wm*32 + mt*16 + (lane >> 2);
            int n0 = bn + wn*32 + nt*8 + (lane & 3)*2;
            float2 bb = make_float2(0.f, 0.f);
            if (bias) bb = *(const float2*)(bias + n0);
            float v[4] = {acc[mt][nt][0]+bb.x, acc[mt][nt][1]+bb.y,
                          acc[mt][nt][2]+bb.x, acc[mt][nt][3]+bb.y};
            size_t i0 = (size_t)m0*Nn + n0;
            size_t i1 = (size_t)(m0+8)*Nn + n0;
            if (EPI == 3) {
                float h0=__bfloat162float(__float2bfloat16_rn(v[0]));
                float h1=__bfloat162float(__float2bfloat16_rn(v[1]));
                float h2=__bfloat162float(__float2bfloat16_rn(v[2]));
                float h3=__bfloat162float(__float2bfloat16_rn(v[3]));
                *(uint32_t*)(Ch + i0) = packbf(h0, h1);
                *(uint32_t*)(Cl + i0) = packbf(v[0]-h0, v[1]-h1);
                *(uint32_t*)(Ch + i1) = packbf(h2, h3);
                *(uint32_t*)(Cl + i1) = packbf(v[2]-h2, v[3]-h3);
            } else {
                if (EPI >= 1) {
                    float2 r0 = *(const float2*)(resid + i0);
                    float2 r1 = *(const float2*)(resid + i1);
                    v[0]+=r0.x; v[1]+=r0.y; v[2]+=r1.x; v[3]+=r1.y;
                }
                if (EPI == 2) {
                    v[0]=tanhf(v[0]); v[1]=tanhf(v[1]);
                    v[2]=tanhf(v[2]); v[3]=tanhf(v[3]);
                }
                *(float2*)(C + i0) = make_float2(v[0], v[1]);
                *(float2*)(C + i1) = make_float2(v[2], v[3]);
            }
        }
}

// ---------------- mma flash attention: 128q/CTA, kv tiles 64, bf16x3 -------
__global__ __launch_bounds__(256) void attn_mma_kernel(
    const __nv_bfloat16* __restrict__ qh, const __nv_bfloat16* __restrict__ ql,
    __nv_bfloat16* __restrict__ aoh, __nv_bfloat16* __restrict__ aol)
{
    __shared__ __nv_bfloat16 sQ[2][128*40];
    __shared__ __nv_bfloat16 sK[2][64*40];
    __shared__ __nv_bfloat16 sV[2][64*40];
    const int qt = blockIdx.x, h = blockIdx.y, bc = blockIdx.z;
    const int t = threadIdx.x, lane = t & 31, w = t >> 5;
    const size_t tokb = (size_t)bc*NSEQ;
    const float scale = 0.17677669529663687f;

    // stage Q (128x32 hi/lo)
#pragma unroll
    for (int r=0;r<2;r++) {
        int f = t + r*256, row = f >> 2, c8 = (f & 3)*8;
        size_t g = (tokb + qt*128 + row)*HID + h*DHEAD + c8;
        *(uint4*)&sQ[0][row*40+c8] = *(const uint4*)(qh + g);
        *(uint4*)&sQ[1][row*40+c8] = *(const uint4*)(ql + g);
    }
    __syncthreads();

    uint32_t qfh[2][4], qfl[2][4];
    {
        const uint32_t q0 = smem_u32(sQ[0]), q1 = smem_u32(sQ[1]);
#pragma unroll
        for (int kc=0;kc<2;kc++) {
            int row = w*16 + (lane & 15), col = kc*16 + (lane >> 4)*8;
            uint32_t o2 = (uint32_t)(row*40 + col)*2;
            ldsm4(q0 + o2, qfh[kc][0],qfh[kc][1],qfh[kc][2],qfh[kc][3]);
            ldsm4(q1 + o2, qfl[kc][0],qfl[kc][1],qfl[kc][2],qfl[kc][3]);
        }
    }

    float o[4][4];
#pragma unroll
    for (int i=0;i<4;i++)
#pragma unroll
        for (int j=0;j<4;j++) o[i][j]=0.f;
    float mrun0=-1e30f, mrun1=-1e30f, lrun0=0.f, lrun1=0.f;
    const uint32_t k0b = smem_u32(sK[0]), k1b = smem_u32(sK[1]);
    const uint32_t v0b = smem_u32(sV[0]), v1b = smem_u32(sV[1]);

    for (int kt=0; kt<16; kt++) {
        __syncthreads();
        {
            int row = t >> 2, c8 = (t & 3)*8;
            size_t g = (tokb + kt*64 + row)*HID + h*DHEAD + c8;
            *(uint4*)&sK[0][row*40+c8] = *(const uint4*)(qh + g + DMODEL);
            *(uint4*)&sK[1][row*40+c8] = *(const uint4*)(ql + g + DMODEL);
            *(uint4*)&sV[0][row*40+c8] = *(const uint4*)(qh + g + 2*DMODEL);
            *(uint4*)&sV[1][row*40+c8] = *(const uint4*)(ql + g + 2*DMODEL);
        }
        __syncthreads();

        float S[8][4];
#pragma unroll
        for (int j=0;j<8;j++)
#pragma unroll
            for (int e=0;e<4;e++) S[j][e]=0.f;
#pragma unroll
        for (int kc=0;kc<2;kc++)
#pragma unroll
            for (int jp=0;jp<4;jp++) {
                int row = jp*16 + ((lane>>4)&1)*8 + (lane&7);
                int col = kc*16 + ((lane>>3)&1)*8;
                uint32_t o2 = (uint32_t)(row*40 + col)*2;
                uint32_t h0,h1,h2,h3, l0,l1,l2,l3;
                ldsm4(k0b + o2, h0,h1,h2,h3);
                ldsm4(k1b + o2, l0,l1,l2,l3);
                mma16816(S[2*jp],   qfh[kc][0],qfh[kc][1],qfh[kc][2],qfh[kc][3], h0,h1);
                mma16816(S[2*jp+1], qfh[kc][0],qfh[kc][1],qfh[kc][2],qfh[kc][3], h2,h3);
                mma16816(S[2*jp],   qfh[kc][0],qfh[kc][1],qfh[kc][2],qfh[kc][3], l0,l1);
                mma16816(S[2*jp+1], qfh[kc][0],qfh[kc][1],qfh[kc][2],qfh[kc][3], l2,l3);
                mma16816(S[2*jp],   qfl[kc][0],qfl[kc][1],qfl[kc][2],qfl[kc][3], h0,h1);
                mma16816(S[2*jp+1], qfl[kc][0],qfl[kc][1],qfl[kc][2],qfl[kc][3], h2,h3);
            }

        // online softmax (rows r=lane>>2 and r+8)
        float mx0=-1e30f, mx1=-1e30f;
#pragma unroll
        for (int j=0;j<8;j++) {
            mx0 = fmaxf(mx0, fmaxf(S[j][0], S[j][1]));
            mx1 = fmaxf(mx1, fmaxf(S[j][2], S[j][3]));
        }
        mx0 *= scale; mx1 *= scale;
        mx0 = fmaxf(mx0, __shfl_xor_sync(0xffffffffu, mx0, 1));
        mx0 = fmaxf(mx0, __shfl_xor_sync(0xffffffffu, mx0, 2));
        mx1 = fmaxf(mx1, __shfl_xor_sync(0xffffffffu, mx1, 1));
        mx1 = fmaxf(mx1, __shfl_xor_sync(0xffffffffu, mx1, 2));
        float mn0 = fmaxf(mrun0, mx0), mn1 = fmaxf(mrun1, mx1);
        float a0 = __expf(mrun0 - mn0), a1 = __expf(mrun1 - mn1);
        mrun0 = mn0; mrun1 = mn1;
#pragma unroll
        for (int nt=0;nt<4;nt++) {
            o[nt][0]*=a0; o[nt][1]*=a0; o[nt][2]*=a1; o[nt][3]*=a1;
        }
        float rs0=0.f, rs1=0.f;
#pragma unroll
        for (int kc2=0;kc2<4;kc2++) {
            int j0 = 2*kc2;
            float p00=__expf(S[j0][0]*scale - mn0), p01=__expf(S[j0][1]*scale - mn0);
            float p02=__expf(S[j0][2]*scale - mn1), p03=__expf(S[j0][3]*scale - mn1);
            float p10=__expf(S[j0+1][0]*scale - mn0), p11=__expf(S[j0+1][1]*scale - mn0);
            float p12=__expf(S[j0+1][2]*scale - mn1), p13=__expf(S[j0+1][3]*scale - mn1);
            rs0 += p00+p01+p10+p11;
            rs1 += p02+p03+p12+p13;
            float q00=__bfloat162float(__float2bfloat16_rn(p00));
            float q01=__bfloat162float(__float2bfloat16_rn(p01));
            float q02=__bfloat162float(__float2bfloat16_rn(p02));
            float q03=__bfloat162float(__float2bfloat16_rn(p03));
            float q10=__bfloat162float(__float2bfloat16_rn(p10));
            float q11=__bfloat162float(__float2bfloat16_rn(p11));
            float q12=__bfloat162float(__float2bfloat16_rn(p12));
            float q13=__bfloat162float(__float2bfloat16_rn(p13));
            uint32_t aph[4] = {packbf(q00,q01), packbf(q02,q03),
                               packbf(q10,q11), packbf(q12,q13)};
            uint32_t apl[4] = {packbf(p00-q00,p01-q01), packbf(p02-q02,p03-q03),
                               packbf(p10-q10,p11-q11), packbf(p12-q12,p13-q13)};
#pragma unroll
            for (int g=0; g<2; g++) {
                int row = kc2*16 + ((lane>>3)&1)*8 + (lane&7);
                int col = g*16 + ((lane>>4)&1)*8;
                uint32_t o2 = (uint32_t)(row*40 + col)*2;
                uint32_t vh0,vh1,vh2,vh3, vl0,vl1,vl2,vl3;
                ldsm4t(v0b + o2, vh0,vh1,vh2,vh3);
                ldsm4t(v1b + o2, vl0,vl1,vl2,vl3);
                mma16816(o[2*g],   aph[0],aph[1],aph[2],aph[3], vh0,vh1);
                mma16816(o[2*g+1], aph[0],aph[1],aph[2],aph[3], vh2,vh3);
                mma16816(o[2*g],   aph[0],aph[1],aph[2],aph[3], vl0,vl1);
                mma16816(o[2*g+1], aph[0],aph[1],aph[2],aph[3], vl2,vl3);
                mma16816(o[2*g],   apl[0],apl[1],apl[2],apl[3], vh0,vh1);
                mma16816(o[2*g+1], apl[0],apl[1],apl[2],apl[3], vh2,vh3);
            }
        }
        rs0 += __shfl_xor_sync(0xffffffffu, rs0, 1);
        rs0 += __shfl_xor_sync(0xffffffffu, rs0, 2);
        rs1 += __shfl_xor_sync(0xffffffffu, rs1, 1);
        rs1 += __shfl_xor_sync(0xffffffffu, rs1, 2);
        lrun0 = lrun0*a0 + rs0;
        lrun1 = lrun1*a1 + rs1;
    }

    // epilogue -> bf16 hi/lo attention output [tok, 256]
    float inv0 = 1.f/lrun0, inv1 = 1.f/lrun1;
    int r0 = qt*128 + w*16 + (lane >> 2);
#pragma unroll
    for (int nt=0; nt<4; nt++) {
        int d = h*DHEAD + nt*8 + (lane & 3)*2;
        size_t i0 = (tokb + r0)*DMODEL + d;
        size_t i1 = (tokb + r0 + 8)*DMODEL + d;
        float v0 = o[nt][0]*inv0, v1 = o[nt][1]*inv0;
        float v2 = o[nt][2]*inv1, v3 = o[nt][3]*inv1;
        float h0=__bfloat162float(__float2bfloat16_rn(v0));
        float h1=__bfloat162float(__float2bfloat16_rn(v1));
        float h2=__bfloat162float(__float2bfloat16_rn(v2));
        float h3=__bfloat162float(__float2bfloat16_rn(v3));
        *(uint32_t*)(aoh + i0) = packbf(h0, h1);
        *(uint32_t*)(aol + i0) = packbf(v0-h0, v1-h1);
        *(uint32_t*)(aoh + i1) = packbf(h2, h3);
        *(uint32_t*)(aol + i1) = packbf(v2-h2, v3-h3);
    }
}

// ---------------- RMS norm: warp/token, bf16 hi/lo output ----------------
__global__ __launch_bounds__(256) void rms_kernel(
    const float* __restrict__ x, const float* __restrict__ w,
    __nv_bfloat16* __restrict__ yh, __nv_bfloat16* __restrict__ yl)
{
    int tok  = blockIdx.x*8 + (threadIdx.x >> 5);
    int lane = threadIdx.x & 31;
    const float* xp = x + (size_t)tok*DMODEL;
    float4 a = *(const float4*)(xp + lane*4);
    float4 b = *(const float4*)(xp + 128 + lane*4);
    float ss = a.x*a.x + a.y*a.y + a.z*a.z + a.w*a.w
             + b.x*b.x + b.y*b.y + b.z*b.z + b.w*b.w;
#pragma unroll
    for (int off=16; off; off>>=1) ss += __shfl_xor_sync(0xffffffffu, ss, off);
    float r = rsqrtf(ss*(1.0f/DMODEL) + 1e-5f);
    float4 wa = *(const float4*)(w + lane*4);
    float4 wb = *(const float4*)(w + 128 + lane*4);
    float va[8] = {a.x*r*wa.x, a.y*r*wa.y, a.z*r*wa.z, a.w*r*wa.w,
                   b.x*r*wb.x, b.y*r*wb.y, b.z*r*wb.z, b.w*r*wb.w};
    size_t o0 = (size_t)tok*DMODEL + lane*4;
    size_t o1 = o0 + 128;
    float h[8];
#pragma unroll
    for (int i=0;i<8;i++) h[i] = __bfloat162float(__float2bfloat16_rn(va[i]));
    *(uint2*)(yh + o0) = make_uint2(packbf(h[0],h[1]), packbf(h[2],h[3]));
    *(uint2*)(yh + o1) = make_uint2(packbf(h[4],h[5]), packbf(h[6],h[7]));
    *(uint2*)(yl + o0) = make_uint2(packbf(va[0]-h[0],va[1]-h[1]), packbf(va[2]-h[2],va[3]-h[3]));
    *(uint2*)(yl + o1) = make_uint2(packbf(va[4]-h[4],va[5]-h[5]), packbf(va[6]-h[6],va[7]-h[7]));
}

// ---------------- swiglu: silu(t1)*t3 -> bf16 hi/lo ----------------
__global__ __launch_bounds__(256) void swiglu_kernel(
    const float* __restrict__ t1, const float* __restrict__ t3,
    __nv_bfloat16* __restrict__ oh, __nv_bfloat16* __restrict__ ol, int n4)
{
    int i = blockIdx.x*256 + threadIdx.x;
    if (i >= n4) return;
    float4 a = ((const float4*)t1)[i];
    float4 b = ((const float4*)t3)[i];
    float v[4];
    v[0] = a.x / (1.f + __expf(-a.x)) * b.x;
    v[1] = a.y / (1.f + __expf(-a.y)) * b.y;
    v[2] = a.z / (1.f + __expf(-a.z)) * b.z;
    v[3] = a.w / (1.f + __expf(-a.w)) * b.w;
    float h[4];
#pragma unroll
    for (int j=0;j<4;j++) h[j] = __bfloat162float(__float2bfloat16_rn(v[j]));
    ((uint2*)oh)[i] = make_uint2(packbf(h[0],h[1]), packbf(h[2],h[3]));
    ((uint2*)ol)[i] = make_uint2(packbf(v[0]-h[0],v[1]-h[1]), packbf(v[2]-h[2],v[3]-h[3]));
}

// ---------------- edge bucketing (single block, deterministic) -------------
__global__ void bucket_kernel(const int* __restrict__ w)
{
    __shared__ int s_is64;
    __shared__ int s_cnt[LLOG];
    __shared__ int s_st[LLOG+1];
    int t = threadIdx.x;
    if (t == 0) {
        int z = 0;
        for (int i=1;i<64;i+=2) z |= w[i];
        s_is64 = (z == 0);
    }
    __syncthreads();
    int is64 = s_is64;
    int cnt = 0;
    for (int e=0;e<NEDGE;e++) {
        int dst = is64 ? w[2*NEDGE + 2*e] : w[NEDGE + e];
        cnt += (dst == t);
    }
    s_cnt[t] = cnt;
    __syncthreads();
    if (t == 0) {
        int acc = 0;
        for (int l=0;l<LLOG;l++) { s_st[l] = acc; acc += s_cnt[l]; }
        s_st[LLOG] = acc;
    }
    __syncthreads();
    g_start[t] = s_st[t];
    if (t == 0) g_start[LLOG] = s_st[LLOG];
    int idx = s_st[t];
    for (int e=0;e<NEDGE;e++) {
        int dst = is64 ? w[2*NEDGE + 2*e] : w[NEDGE + e];
        if (dst == t) {
            int src = is64 ? w[2*e] : w[e];
            g_order[idx++] = src;
        }
    }
}

// ---------------- scatter-multiply ----------------
__global__ __launch_bounds__(256) void scatterprod_kernel(
    const float* __restrict__ x3, float* __restrict__ lout)
{
    int l = blockIdx.x, bc = blockIdx.y, d = threadIdx.x;
    int s = g_start[l], e = g_start[l+1];
    float p = 1.f;
    const float* base = x3 + (size_t)bc*NSEQ*DMODEL + d;
    for (int i=s; i<e; i++) p *= base[(size_t)g_order[i]*DMODEL];
    lout[((size_t)bc*LLOG + l)*DMODEL + d] = p;
}

// ---------------- head ----------------
__global__ __launch_bounds__(256) void head_kernel(
    const float* __restrict__ l2, const float* __restrict__ hw,
    const float* __restrict__ hb, float* __restrict__ out)
{
    int tok  = blockIdx.x*8 + (threadIdx.x >> 5);
    int lane = threadIdx.x & 31;
    const float* p = l2 + (size_t)tok*DMODEL;
    float s = 0.f;
#pragma unroll
    for (int i=0;i<8;i++) s += p[lane + 32*i]*hw[lane + 32*i];
#pragma unroll
    for (int off=16; off; off>>=1) s += __shfl_xor_sync(0xffffffffu, s, off);
    if (lane == 0) out[tok] = s + hb[0];
}

// ---------------- host orchestration ----------------
// weight offsets in g_whi/g_wlo
#define WO_INPROJ 0
#define WO_OUT    196608
#define WO_FW1    262144
#define WO_FW3    458752
#define WO_FW2    655360
#define WO_DW1    851968
#define WO_DW3    1048576
#define WO_DW2    1245184
#define WO_LW1    1441792
#define WO_LW3    1638400
#define WO_LW2    1835008

static __nv_bfloat16 *h_whi, *h_wlo;

static inline void wconv(const float* src, size_t off, int n) {
    wconv_kernel<<<(n/4+255)/256,256>>>(src, h_whi+off, h_wlo+off, n/4);
}

static inline void launch_bgemm(int epi, const __nv_bfloat16* Ah, const __nv_bfloat16* Al,
                                size_t woff, const float* bias, const float* resid,
                                float* C, __nv_bfloat16* Ch, __nv_bfloat16* Cl,
                                int M, int Nn, int K)
{
    dim3 grid(Nn/128, M/128);
    const __nv_bfloat16* Wh = h_whi + woff;
    const __nv_bfloat16* Wl = h_wlo + woff;
    if (epi == 0) {
        cudaFuncSetAttribute(bgemm_kernel<0>, cudaFuncAttributeMaxDynamicSharedMemorySize, BG_SMEM);
        bgemm_kernel<0><<<grid,512,BG_SMEM>>>(Ah,Al,Wh,Wl,bias,resid,C,Ch,Cl,M,Nn,K);
    } else if (epi == 1) {
        cudaFuncSetAttribute(bgemm_kernel<1>, cudaFuncAttributeMaxDynamicSharedMemorySize, BG_SMEM);
        bgemm_kernel<1><<<grid,512,BG_SMEM>>>(Ah,Al,Wh,Wl,bias,resid,C,Ch,Cl,M,Nn,K);
    } else if (epi == 2) {
        cudaFuncSetAttribute(bgemm_kernel<2>, cudaFuncAttributeMaxDynamicSharedMemorySize, BG_SMEM);
        bgemm_kernel<2><<<grid,512,BG_SMEM>>>(Ah,Al,Wh,Wl,bias,resid,C,Ch,Cl,M,Nn,K);
    } else {
        cudaFuncSetAttribute(bgemm_kernel<3>, cudaFuncAttributeMaxDynamicSharedMemorySize, BG_SMEM);
        bgemm_kernel<3><<<grid,512,BG_SMEM>>>(Ah,Al,Wh,Wl,bias,resid,C,Ch,Cl,M,Nn,K);
    }
}

extern "C" void kernel_launch(void* const* d_in, const int* in_sizes, int n_in,
                              void* d_out, int out_size)
{
    (void)in_sizes; (void)n_in; (void)out_size;
    const float* v           = (const float*)d_in[0];
    const int*   d2l         = (const int*)  d_in[1];
    const float* attn_norm_w = (const float*)d_in[2];
    const float* in_proj_w   = (const float*)d_in[3];
    const float* in_proj_b   = (const float*)d_in[4];
    const float* out_w       = (const float*)d_in[5];
    const float* out_b       = (const float*)d_in[6];
    const float* ffn_norm_w  = (const float*)d_in[7];
    const float* ffn_w1      = (const float*)d_in[8];
    const float* ffn_w2      = (const float*)d_in[9];
    const float* ffn_w3      = (const float*)d_in[10];
    const float* du_norm_w   = (const float*)d_in[11];
    const float* du_w1       = (const float*)d_in[12];
    const float* du_w2       = (const float*)d_in[13];
    const float* du_w3       = (const float*)d_in[14];
    const float* lu_norm_w   = (const float*)d_in[15];
    const float* lu_w1       = (const float*)d_in[16];
    const float* lu_w2       = (const float*)d_in[17];
    const float* lu_w3       = (const float*)d_in[18];
    const float* head_w      = (const float*)d_in[19];
    const float* head_b      = (const float*)d_in[20];
    float* out = (float*)d_out;

    float *buf1, *buf2, *a, *x2, *x3, *lb, *l2;
    __nv_bfloat16 *xnh, *xnl, *qkvh, *qkvl, *t1h, *t1l, *aoh, *aol;
    cudaGetSymbolAddress((void**)&buf1, g_buf1);
    cudaGetSymbolAddress((void**)&buf2, g_buf2);
    cudaGetSymbolAddress((void**)&a,    g_a);
    cudaGetSymbolAddress((void**)&x2,   g_x2);
    cudaGetSymbolAddress((void**)&x3,   g_x3);
    cudaGetSymbolAddress((void**)&lb,   g_l);
    cudaGetSymbolAddress((void**)&l2,   g_l2);
    cudaGetSymbolAddress((void**)&xnh,  g_xnh);
    cudaGetSymbolAddress((void**)&xnl,  g_xnl);
    cudaGetSymbolAddress((void**)&qkvh, g_qkvh);
    cudaGetSymbolAddress((void**)&qkvl, g_qkvl);
    cudaGetSymbolAddress((void**)&t1h,  g_t1h);
    cudaGetSymbolAddress((void**)&t1l,  g_t1l);
    cudaGetSymbolAddress((void**)&aoh,  g_aoh);
    cudaGetSymbolAddress((void**)&aol,  g_aol);
    cudaGetSymbolAddress((void**)&h_whi, g_whi);
    cudaGetSymbolAddress((void**)&h_wlo, g_wlo);

    // 0) weight splits
    wconv(in_proj_w, WO_INPROJ, 768*256);
    wconv(out_w,     WO_OUT,    256*256);
    wconv(ffn_w1,    WO_FW1,    768*256);
    wconv(ffn_w3,    WO_FW3,    768*256);
    wconv(ffn_w2,    WO_FW2,    256*768);
    wconv(du_w1,     WO_DW1,    768*256);
    wconv(du_w3,     WO_DW3,    768*256);
    wconv(du_w2,     WO_DW2,    256*768);
    wconv(lu_w1,     WO_LW1,    768*256);
    wconv(lu_w3,     WO_LW3,    768*256);
    wconv(lu_w2,     WO_LW2,    256*768);
    bucket_kernel<<<1,256>>>(d2l);

    // 1) attn pre-norm -> bf16 hi/lo
    rms_kernel<<<NTOK/8,256>>>(v, attn_norm_w, xnh, xnl);
    // 2) qkv projection -> bf16 hi/lo
    launch_bgemm(3, xnh, xnl, WO_INPROJ, in_proj_b, nullptr, nullptr, qkvh, qkvl, NTOK, HID, DMODEL);
    // 3) mma attention -> bf16 hi/lo
    { dim3 g(NSEQ/128, NHEAD, BC); attn_mma_kernel<<<g,256>>>(qkvh, qkvl, aoh, aol); }
    // 4) out projection + bias + residual v -> a (fp32)
    launch_bgemm(1, aoh, aol, WO_OUT, out_b, v, a, nullptr, nullptr, NTOK, DMODEL, DMODEL);
    // 5) FFN
    rms_kernel<<<NTOK/8,256>>>(a, ffn_norm_w, xnh, xnl);
    launch_bgemm(0, xnh, xnl, WO_FW1, nullptr, nullptr, buf1, nullptr, nullptr, NTOK, HID, DMODEL);
    launch_bgemm(0, xnh, xnl, WO_FW3, nullptr, nullptr, buf2, nullptr, nullptr, NTOK, HID, DMODEL);
    swiglu_kernel<<<(NTOK*HID/4+255)/256,256>>>(buf1, buf2, t1h, t1l, NTOK*HID/4);
    launch_bgemm(1, t1h, t1l, WO_FW2, nullptr, a, x2, nullptr, nullptr, NTOK, DMODEL, HID);
    // 6) du block with tanh
    rms_kernel<<<NTOK/8,256>>>(x2, du_norm_w, xnh, xnl);
    launch_bgemm(0, xnh, xnl, WO_DW1, nullptr, nullptr, buf1, nullptr, nullptr, NTOK, HID, DMODEL);
    launch_bgemm(0, xnh, xnl, WO_DW3, nullptr, nullptr, buf2, nullptr, nullptr, NTOK, HID, DMODEL);
    swiglu_kernel<<<(NTOK*HID/4+255)/256,256>>>(buf1, buf2, t1h, t1l, NTOK*HID/4);
    launch_bgemm(2, t1h, t1l, WO_DW2, nullptr, x2, x3, nullptr, nullptr, NTOK, DMODEL, HID);
    // 7) scatter-multiply into l
    { dim3 g(LLOG, BC); scatterprod_kernel<<<g,256>>>(x3, lb); }
    // 8) lu block
    rms_kernel<<<NTOKL/8,256>>>(lb, lu_norm_w, xnh, xnl);
    launch_bgemm(0, xnh, xnl, WO_LW1, nullptr, nullptr, buf1, nullptr, nullptr, NTOKL, HID, DMODEL);
    launch_bgemm(0, xnh, xnl, WO_LW3, nullptr, nullptr, buf2, nullptr, nullptr, NTOKL, HID, DMODEL);
    swiglu_kernel<<<(NTOKL*HID/4+255)/256,256>>>(buf1, buf2, t1h, t1l, NTOKL*HID/4);
    launch_bgemm(1, t1h, t1l, WO_LW2, nullptr, lb, l2, nullptr, nullptr, NTOKL, DMODEL, HID);
    // 9) head
    head_kernel<<<NTOKL/8,256>>>(l2, head_w, head_b, out);
}

// round 9
// speedup vs baseline: 2.4568x; 1.1856x over previous
#include <cuda_runtime.h>
#include <cuda_bf16.h>
#include <math.h>
#include <stdint.h>

// ---------------- problem constants ----------------
#define BC    32
#define NSEQ  1024
#define DMODEL 256
#define NHEAD 8
#define DHEAD 32
#define HID   768
#define NEDGE 8192
#define LLOG  256
#define NTOK  (BC*NSEQ)   // 32768
#define NTOKL (BC*LLOG)   // 8192
#define WTOT  2031616     // total weight elements

// ---------------- scratch (__device__ globals; no allocs) ----------------
__device__ float g_buf1[NTOK*HID];      // t1 fp32 (w1 out)
__device__ float g_buf2[NTOK*HID];      // t3 fp32 (w3 out)
__device__ float g_a   [NTOK*DMODEL];
__device__ float g_x2  [NTOK*DMODEL];
__device__ float g_x3  [NTOK*DMODEL];
__device__ float g_l   [NTOKL*DMODEL];
__device__ float g_l2  [NTOKL*DMODEL];
__device__ int   g_start[LLOG+1];
__device__ int   g_order[NEDGE];
// bf16 hi/lo activations
__device__ __nv_bfloat16 g_xnh[NTOK*DMODEL], g_xnl[NTOK*DMODEL];
__device__ __nv_bfloat16 g_qkvh[NTOK*HID],  g_qkvl[NTOK*HID];
__device__ __nv_bfloat16 g_t1h[NTOK*HID],   g_t1l[NTOK*HID];
__device__ __nv_bfloat16 g_aoh[NTOK*DMODEL], g_aol[NTOK*DMODEL];
// bf16 hi/lo weights
__device__ __nv_bfloat16 g_whi[WTOT], g_wlo[WTOT];

// ================= mma helpers =================
__device__ __forceinline__ uint32_t smem_u32(const void* p) {
    uint32_t a;
    asm("{ .reg .u64 t; cvta.to.shared.u64 t, %1; cvt.u32.u64 %0, t; }"
        : "=r"(a) : "l"(p));
    return a;
}
__device__ __forceinline__ void ldsm4(uint32_t addr, uint32_t& r0, uint32_t& r1,
                                      uint32_t& r2, uint32_t& r3) {
    asm volatile("ldmatrix.sync.aligned.m8n8.x4.shared.b16 {%0,%1,%2,%3}, [%4];"
                 : "=r"(r0), "=r"(r1), "=r"(r2), "=r"(r3) : "r"(addr));
}
__device__ __forceinline__ void ldsm4t(uint32_t addr, uint32_t& r0, uint32_t& r1,
                                       uint32_t& r2, uint32_t& r3) {
    asm volatile("ldmatrix.sync.aligned.m8n8.x4.trans.shared.b16 {%0,%1,%2,%3}, [%4];"
                 : "=r"(r0), "=r"(r1), "=r"(r2), "=r"(r3) : "r"(addr));
}
__device__ __forceinline__ void mma16816(float* d, uint32_t a0, uint32_t a1,
                                         uint32_t a2, uint32_t a3,
                                         uint32_t b0, uint32_t b1) {
    asm volatile(
        "mma.sync.aligned.m16n8k16.row.col.f32.bf16.bf16.f32 "
        "{%0,%1,%2,%3}, {%4,%5,%6,%7}, {%8,%9}, {%0,%1,%2,%3};"
        : "+f"(d[0]), "+f"(d[1]), "+f"(d[2]), "+f"(d[3])
        : "r"(a0), "r"(a1), "r"(a2), "r"(a3), "r"(b0), "r"(b1));
}
__device__ __forceinline__ uint32_t packbf(float x, float y) {
    __nv_bfloat162 h = __floats2bfloat162_rn(x, y);
    return *(uint32_t*)&h;
}
__device__ __forceinline__ void cpasync16(uint32_t saddr, const void* g) {
    asm volatile("cp.async.cg.shared.global [%0], [%1], 16;" :: "r"(saddr), "l"(g));
}
__device__ __forceinline__ void cpcommit() {
    asm volatile("cp.async.commit_group;");
}

// ---------------- batched weight split: one launch for all 11 weights ------
// region sizes in float4 units; boundaries precomputed.
__global__ __launch_bounds__(256) void wconv_all_kernel(
    const float* __restrict__ s0, const float* __restrict__ s1,
    const float* __restrict__ s2, const float* __restrict__ s3,
    const float* __restrict__ s4, const float* __restrict__ s5,
    const float* __restrict__ s6, const float* __restrict__ s7,
    const float* __restrict__ s8, const float* __restrict__ s9,
    const float* __restrict__ s10,
    __nv_bfloat16* __restrict__ dh, __nv_bfloat16* __restrict__ dl)
{
    int i = blockIdx.x*256 + threadIdx.x;          // float4 index into packed space
    const int B0=49152, B1=65536, B2=114688, B3=163840, B4=212992, B5=262144,
              B6=311296, B7=360448, B8=409600, B9=458752, B10=507904;
    if (i >= B10) return;
    const float* src; int base;
    if      (i < B0) { src = s0;  base = 0;  }
    else if (i < B1) { src = s1;  base = B0; }
    else if (i < B2) { src = s2;  base = B1; }
    else if (i < B3) { src = s3;  base = B2; }
    else if (i < B4) { src = s4;  base = B3; }
    else if (i < B5) { src = s5;  base = B4; }
    else if (i < B6) { src = s6;  base = B5; }
    else if (i < B7) { src = s7;  base = B6; }
    else if (i < B8) { src = s8;  base = B7; }
    else if (i < B9) { src = s9;  base = B8; }
    else             { src = s10; base = B9; }
    float4 v = ((const float4*)src)[i - base];
    float h0=__bfloat162float(__float2bfloat16_rn(v.x));
    float h1=__bfloat162float(__float2bfloat16_rn(v.y));
    float h2=__bfloat162float(__float2bfloat16_rn(v.z));
    float h3=__bfloat162float(__float2bfloat16_rn(v.w));
    ((uint2*)dh)[i] = make_uint2(packbf(h0,h1), packbf(h2,h3));
    ((uint2*)dl)[i] = make_uint2(packbf(v.x-h0,v.y-h1), packbf(v.z-h2,v.w-h3));
}

// ---------------- bf16 GEMM: C[M,N] = (Ah+Al)(Wh+Wl)^T 3-term ----------
// CTA 128x128, BK=32, 256 threads (8 warps: 2 wm x 4 wn), warp tile 64x32.
// EPI: 0 fp32(+bias); 1 fp32(+bias+resid); 2 fp32 tanh(+bias+resid); 3 bf16 hi/lo (+bias)
#define BGS 40
#define BARR (128*BGS)
#define BBUFE (4*BARR)
#define BG_SMEM (2*BBUFE*2)

template<int EPI>
__global__ __launch_bounds__(256) void bgemm_kernel(
    const __nv_bfloat16* __restrict__ Ah, const __nv_bfloat16* __restrict__ Al,
    const __nv_bfloat16* __restrict__ Wh, const __nv_bfloat16* __restrict__ Wl,
    const float* __restrict__ bias, const float* __restrict__ resid,
    float* __restrict__ C, __nv_bfloat16* __restrict__ Ch,
    __nv_bfloat16* __restrict__ Cl, int M, int Nn, int K)
{
    extern __shared__ __nv_bfloat16 sm[];
    const int t = threadIdx.x, lane = t & 31, wid = t >> 5;
    const int wm = wid >> 2, wn = wid & 3;        // 2 x 4 warps, tile 64x32
    const int bm = blockIdx.y * 128, bn = blockIdx.x * 128;
    const uint32_t sbase = smem_u32(sm);
    const int nc = K / 32;

    float acc[4][4][4];
#pragma unroll
    for (int i=0;i<4;i++)
#pragma unroll
        for (int j=0;j<4;j++)
#pragma unroll
            for (int e=0;e<4;e++) acc[i][j][e]=0.f;

    auto issue = [&](int c) {
#pragma unroll
        for (int r=0;r<2;r++) {
            int s = t + r*256;                     // 0..511 16B segments per array
            int row = s >> 2, col8 = (s & 3) * 8;
            uint32_t soff = sbase + (uint32_t)(c & 1)*(BBUFE*2)
                          + (uint32_t)(row*BGS + col8)*2;
            size_t ga = (size_t)(bm + row)*K + c*32 + col8;
            size_t gw = (size_t)(bn + row)*K + c*32 + col8;
            cpasync16(soff + 0*BARR*2, Ah + ga);
            cpasync16(soff + 1*BARR*2, Al + ga);
            cpasync16(soff + 2*BARR*2, Wh + gw);
            cpasync16(soff + 3*BARR*2, Wl + gw);
        }
        cpcommit();
    };
    issue(0);

    for (int c = 0; c < nc; c++) {
        if (c + 1 < nc) {
            issue(c + 1);
            asm volatile("cp.async.wait_group 1;");
        } else {
            asm volatile("cp.async.wait_group 0;");
        }
        __syncthreads();
        uint32_t base = sbase + (uint32_t)(c & 1)*(BBUFE*2);
#pragma unroll
        for (int ks = 0; ks < 2; ks++) {
            uint32_t ahf[4][4], alf[4][4], bhf[2][4], blf[2][4];
            int rl = lane & 15, ch = (lane >> 4) * 8;
            int col = ks*16 + ch;
#pragma unroll
            for (int mt=0; mt<4; mt++) {
                int row = wm*64 + mt*16 + rl;
                uint32_t o = (uint32_t)(row*BGS + col)*2;
                ldsm4(base + 0*BARR*2 + o, ahf[mt][0],ahf[mt][1],ahf[mt][2],ahf[mt][3]);
                ldsm4(base + 1*BARR*2 + o, alf[mt][0],alf[mt][1],alf[mt][2],alf[mt][3]);
            }
#pragma unroll
            for (int g=0; g<2; g++) {
                int row = wn*32 + g*16 + rl;
                uint32_t o = (uint32_t)(row*BGS + col)*2;
                ldsm4(base + 2*BARR*2 + o, bhf[g][0],bhf[g][1],bhf[g][2],bhf[g][3]);
                ldsm4(base + 3*BARR*2 + o, blf[g][0],blf[g][1],blf[g][2],blf[g][3]);
            }
#pragma unroll
            for (int mt=0; mt<4; mt++)
#pragma unroll
                for (int g=0; g<2; g++)
#pragma unroll
                    for (int sub=0; sub<2; sub++) {
                        int nt = g*2 + sub;
                        uint32_t h0 = sub ? bhf[g][1] : bhf[g][0];
                        uint32_t h1 = sub ? bhf[g][3] : bhf[g][2];
                        uint32_t l0 = sub ? blf[g][1] : blf[g][0];
                        uint32_t l1 = sub ? blf[g][3] : blf[g][2];
                        mma16816(acc[mt][nt], ahf[mt][0],ahf[mt][1],ahf[mt][2],ahf[mt][3], h0,h1);
                        mma16816(acc[mt][nt], ahf[mt][0],ahf[mt][1],ahf[mt][2],ahf[mt][3], l0,l1);
                        mma16816(acc[mt][nt], alf[mt][0],alf[mt][1],alf[mt][2],alf[mt][3], h0,h1);
                    }
        }
        __syncthreads();
    }

    // epilogue
#pragma unroll
    for (int mt=0; mt<4; mt++)
#pragma unroll
        for (int nt=0; nt<4; nt++) {
            int m0 = bm + wm*64 + mt*16 + (lane >> 2);
            int n0 = bn + wn*32 + nt*8 + (lane & 3)*2;
            float2 bb = make_float2(0.f, 0.f);
            if (bias) bb = *(const float2*)(bias + n0);
            float v[4] = {acc[mt][nt][0]+bb.x, acc[mt][nt][1]+bb.y,
                          acc[mt][nt][2]+bb.x, acc[mt][nt][3]+bb.y};
            size_t i0 = (size_t)m0*Nn + n0;
            size_t i1 = (size_t)(m0+8)*Nn + n0;
            if (EPI == 3) {
                float h0=__bfloat162float(__float2bfloat16_rn(v[0]));
                float h1=__bfloat162float(__float2bfloat16_rn(v[1]));
                float h2=__bfloat162float(__float2bfloat16_rn(v[2]));
                float h3=__bfloat162float(__float2bfloat16_rn(v[3]));
                *(uint32_t*)(Ch + i0) = packbf(h0, h1);
                *(uint32_t*)(Cl + i0) = packbf(v[0]-h0, v[1]-h1);
                *(uint32_t*)(Ch + i1) = packbf(h2, h3);
                *(uint32_t*)(Cl + i1) = packbf(v[2]-h2, v[3]-h3);
            } else {
                if (EPI >= 1) {
                    float2 r0 = *(const float2*)(resid + i0);
                    float2 r1 = *(const float2*)(resid + i1);
                    v[0]+=r0.x; v[1]+=r0.y; v[2]+=r1.x; v[3]+=r1.y;
                }
                if (EPI == 2) {
                    v[0]=tanhf(v[0]); v[1]=tanhf(v[1]);
                    v[2]=tanhf(v[2]); v[3]=tanhf(v[3]);
                }
                *(float2*)(C + i0) = make_float2(v[0], v[1]);
                *(float2*)(C + i1) = make_float2(v[2], v[3]);
            }
        }
}

// ---------------- mma flash attention: 128q/CTA, kv tiles 64, bf16x3 -------
__global__ __launch_bounds__(256) void attn_mma_kernel(
    const __nv_bfloat16* __restrict__ qh, const __nv_bfloat16* __restrict__ ql,
    __nv_bfloat16* __restrict__ aoh, __nv_bfloat16* __restrict__ aol)
{
    __shared__ __nv_bfloat16 sQ[2][128*40];
    __shared__ __nv_bfloat16 sK[2][64*40];
    __shared__ __nv_bfloat16 sV[2][64*40];
    const int qt = blockIdx.x, h = blockIdx.y, bc = blockIdx.z;
    const int t = threadIdx.x, lane = t & 31, w = t >> 5;
    const size_t tokb = (size_t)bc*NSEQ;
    const float scale = 0.17677669529663687f;

    // stage Q (128x32 hi/lo)
#pragma unroll
    for (int r=0;r<2;r++) {
        int f = t + r*256, row = f >> 2, c8 = (f & 3)*8;
        size_t g = (tokb + qt*128 + row)*HID + h*DHEAD + c8;
        *(uint4*)&sQ[0][row*40+c8] = *(const uint4*)(qh + g);
        *(uint4*)&sQ[1][row*40+c8] = *(const uint4*)(ql + g);
    }
    __syncthreads();

    uint32_t qfh[2][4], qfl[2][4];
    {
        const uint32_t q0 = smem_u32(sQ[0]), q1 = smem_u32(sQ[1]);
#pragma unroll
        for (int kc=0;kc<2;kc++) {
            int row = w*16 + (lane & 15), col = kc*16 + (lane >> 4)*8;
            uint32_t o2 = (uint32_t)(row*40 + col)*2;
            ldsm4(q0 + o2, qfh[kc][0],qfh[kc][1],qfh[kc][2],qfh[kc][3]);
            ldsm4(q1 + o2, qfl[kc][0],qfl[kc][1],qfl[kc][2],qfl[kc][3]);
        }
    }

    float o[4][4];
#pragma unroll
    for (int i=0;i<4;i++)
#pragma unroll
        for (int j=0;j<4;j++) o[i][j]=0.f;
    float mrun0=-1e30f, mrun1=-1e30f, lrun0=0.f, lrun1=0.f;
    const uint32_t k0b = smem_u32(sK[0]), k1b = smem_u32(sK[1]);
    const uint32_t v0b = smem_u32(sV[0]), v1b = smem_u32(sV[1]);

    for (int kt=0; kt<16; kt++) {
        __syncthreads();
        {
            int row = t >> 2, c8 = (t & 3)*8;
            size_t g = (tokb + kt*64 + row)*HID + h*DHEAD + c8;
            *(uint4*)&sK[0][row*40+c8] = *(const uint4*)(qh + g + DMODEL);
            *(uint4*)&sK[1][row*40+c8] = *(const uint4*)(ql + g + DMODEL);
            *(uint4*)&sV[0][row*40+c8] = *(const uint4*)(qh + g + 2*DMODEL);
            *(uint4*)&sV[1][row*40+c8] = *(const uint4*)(ql + g + 2*DMODEL);
        }
        __syncthreads();

        float S[8][4];
#pragma unroll
        for (int j=0;j<8;j++)
#pragma unroll
            for (int e=0;e<4;e++) S[j][e]=0.f;
#pragma unroll
        for (int kc=0;kc<2;kc++)
#pragma unroll
            for (int jp=0;jp<4;jp++) {
                int row = jp*16 + ((lane>>4)&1)*8 + (lane&7);
                int col = kc*16 + ((lane>>3)&1)*8;
                uint32_t o2 = (uint32_t)(row*40 + col)*2;
                uint32_t h0,h1,h2,h3, l0,l1,l2,l3;
                ldsm4(k0b + o2, h0,h1,h2,h3);
                ldsm4(k1b + o2, l0,l1,l2,l3);
                mma16816(S[2*jp],   qfh[kc][0],qfh[kc][1],qfh[kc][2],qfh[kc][3], h0,h1);
                mma16816(S[2*jp+1], qfh[kc][0],qfh[kc][1],qfh[kc][2],qfh[kc][3], h2,h3);
                mma16816(S[2*jp],   qfh[kc][0],qfh[kc][1],qfh[kc][2],qfh[kc][3], l0,l1);
                mma16816(S[2*jp+1], qfh[kc][0],qfh[kc][1],qfh[kc][2],qfh[kc][3], l2,l3);
                mma16816(S[2*jp],   qfl[kc][0],qfl[kc][1],qfl[kc][2],qfl[kc][3], h0,h1);
                mma16816(S[2*jp+1], qfl[kc][0],qfl[kc][1],qfl[kc][2],qfl[kc][3], h2,h3);
            }

        // online softmax (rows r=lane>>2 and r+8)
        float mx0=-1e30f, mx1=-1e30f;
#pragma unroll
        for (int j=0;j<8;j++) {
            mx0 = fmaxf(mx0, fmaxf(S[j][0], S[j][1]));
            mx1 = fmaxf(mx1, fmaxf(S[j][2], S[j][3]));
        }
        mx0 *= scale; mx1 *= scale;
        mx0 = fmaxf(mx0, __shfl_xor_sync(0xffffffffu, mx0, 1));
        mx0 = fmaxf(mx0, __shfl_xor_sync(0xffffffffu, mx0, 2));
        mx1 = fmaxf(mx1, __shfl_xor_sync(0xffffffffu, mx1, 1));
        mx1 = fmaxf(mx1, __shfl_xor_sync(0xffffffffu, mx1, 2));
        float mn0 = fmaxf(mrun0, mx0), mn1 = fmaxf(mrun1, mx1);
        float a0 = __expf(mrun0 - mn0), a1 = __expf(mrun1 - mn1);
        mrun0 = mn0; mrun1 = mn1;
#pragma unroll
        for (int nt=0;nt<4;nt++) {
            o[nt][0]*=a0; o[nt][1]*=a0; o[nt][2]*=a1; o[nt][3]*=a1;
        }
        float rs0=0.f, rs1=0.f;
#pragma unroll
        for (int kc2=0;kc2<4;kc2++) {
            int j0 = 2*kc2;
            float p00=__expf(S[j0][0]*scale - mn0), p01=__expf(S[j0][1]*scale - mn0);
            float p02=__expf(S[j0][2]*scale - mn1), p03=__expf(S[j0][3]*scale - mn1);
            float p10=__expf(S[j0+1][0]*scale - mn0), p11=__expf(S[j0+1][1]*scale - mn0);
            float p12=__expf(S[j0+1][2]*scale - mn1), p13=__expf(S[j0+1][3]*scale - mn1);
            rs0 += p00+p01+p10+p11;
            rs1 += p02+p03+p12+p13;
            float q00=__bfloat162float(__float2bfloat16_rn(p00));
            float q01=__bfloat162float(__float2bfloat16_rn(p01));
            float q02=__bfloat162float(__float2bfloat16_rn(p02));
            float q03=__bfloat162float(__float2bfloat16_rn(p03));
            float q10=__bfloat162float(__float2bfloat16_rn(p10));
            float q11=__bfloat162float(__float2bfloat16_rn(p11));
            float q12=__bfloat162float(__float2bfloat16_rn(p12));
            float q13=__bfloat162float(__float2bfloat16_rn(p13));
            uint32_t aph[4] = {packbf(q00,q01), packbf(q02,q03),
                               packbf(q10,q11), packbf(q12,q13)};
            uint32_t apl[4] = {packbf(p00-q00,p01-q01), packbf(p02-q02,p03-q03),
                               packbf(p10-q10,p11-q11), packbf(p12-q12,p13-q13)};
#pragma unroll
            for (int g=0; g<2; g++) {
                int row = kc2*16 + ((lane>>3)&1)*8 + (lane&7);
                int col = g*16 + ((lane>>4)&1)*8;
                uint32_t o2 = (uint32_t)(row*40 + col)*2;
                uint32_t vh0,vh1,vh2,vh3, vl0,vl1,vl2,vl3;
                ldsm4t(v0b + o2, vh0,vh1,vh2,vh3);
                ldsm4t(v1b + o2, vl0,vl1,vl2,vl3);
                mma16816(o[2*g],   aph[0],aph[1],aph[2],aph[3], vh0,vh1);
                mma16816(o[2*g+1], aph[0],aph[1],aph[2],aph[3], vh2,vh3);
                mma16816(o[2*g],   aph[0],aph[1],aph[2],aph[3], vl0,vl1);
                mma16816(o[2*g+1], aph[0],aph[1],aph[2],aph[3], vl2,vl3);
                mma16816(o[2*g],   apl[0],apl[1],apl[2],apl[3], vh0,vh1);
                mma16816(o[2*g+1], apl[0],apl[1],apl[2],apl[3], vh2,vh3);
            }
        }
        rs0 += __shfl_xor_sync(0xffffffffu, rs0, 1);
        rs0 += __shfl_xor_sync(0xffffffffu, rs0, 2);
        rs1 += __shfl_xor_sync(0xffffffffu, rs1, 1);
        rs1 += __shfl_xor_sync(0xffffffffu, rs1, 2);
        lrun0 = lrun0*a0 + rs0;
        lrun1 = lrun1*a1 + rs1;
    }

    // epilogue -> bf16 hi/lo attention output [tok, 256]
    float inv0 = 1.f/lrun0, inv1 = 1.f/lrun1;
    int r0 = qt*128 + w*16 + (lane >> 2);
#pragma unroll
    for (int nt=0; nt<4; nt++) {
        int d = h*DHEAD + nt*8 + (lane & 3)*2;
        size_t i0 = (tokb + r0)*DMODEL + d;
        size_t i1 = (tokb + r0 + 8)*DMODEL + d;
        float v0 = o[nt][0]*inv0, v1 = o[nt][1]*inv0;
        float v2 = o[nt][2]*inv1, v3 = o[nt][3]*inv1;
        float h0=__bfloat162float(__float2bfloat16_rn(v0));
        float h1=__bfloat162float(__float2bfloat16_rn(v1));
        float h2=__bfloat162float(__float2bfloat16_rn(v2));
        float h3=__bfloat162float(__float2bfloat16_rn(v3));
        *(uint32_t*)(aoh + i0) = packbf(h0, h1);
        *(uint32_t*)(aol + i0) = packbf(v0-h0, v1-h1);
        *(uint32_t*)(aoh + i1) = packbf(h2, h3);
        *(uint32_t*)(aol + i1) = packbf(v2-h2, v3-h3);
    }
}

// ---------------- RMS norm: warp/token, bf16 hi/lo output ----------------
__global__ __launch_bounds__(256) void rms_kernel(
    const float* __restrict__ x, const float* __restrict__ w,
    __nv_bfloat16* __restrict__ yh, __nv_bfloat16* __restrict__ yl)
{
    int tok  = blockIdx.x*8 + (threadIdx.x >> 5);
    int lane = threadIdx.x & 31;
    const float* xp = x + (size_t)tok*DMODEL;
    float4 a = *(const float4*)(xp + lane*4);
    float4 b = *(const float4*)(xp + 128 + lane*4);
    float ss = a.x*a.x + a.y*a.y + a.z*a.z + a.w*a.w
             + b.x*b.x + b.y*b.y + b.z*b.z + b.w*b.w;
#pragma unroll
    for (int off=16; off; off>>=1) ss += __shfl_xor_sync(0xffffffffu, ss, off);
    float r = rsqrtf(ss*(1.0f/DMODEL) + 1e-5f);
    float4 wa = *(const float4*)(w + lane*4);
    float4 wb = *(const float4*)(w + 128 + lane*4);
    float va[8] = {a.x*r*wa.x, a.y*r*wa.y, a.z*r*wa.z, a.w*r*wa.w,
                   b.x*r*wb.x, b.y*r*wb.y, b.z*r*wb.z, b.w*r*wb.w};
    size_t o0 = (size_t)tok*DMODEL + lane*4;
    size_t o1 = o0 + 128;
    float h[8];
#pragma unroll
    for (int i=0;i<8;i++) h[i] = __bfloat162float(__float2bfloat16_rn(va[i]));
    *(uint2*)(yh + o0) = make_uint2(packbf(h[0],h[1]), packbf(h[2],h[3]));
    *(uint2*)(yh + o1) = make_uint2(packbf(h[4],h[5]), packbf(h[6],h[7]));
    *(uint2*)(yl + o0) = make_uint2(packbf(va[0]-h[0],va[1]-h[1]), packbf(va[2]-h[2],va[3]-h[3]));
    *(uint2*)(yl + o1) = make_uint2(packbf(va[4]-h[4],va[5]-h[5]), packbf(va[6]-h[6],va[7]-h[7]));
}

// ---------------- swiglu: silu(t1)*t3 -> bf16 hi/lo ----------------
__global__ __launch_bounds__(256) void swiglu_kernel(
    const float* __restrict__ t1, const float* __restrict__ t3,
    __nv_bfloat16* __restrict__ oh, __nv_bfloat16* __restrict__ ol, int n4)
{
    int i = blockIdx.x*256 + threadIdx.x;
    if (i >= n4) return;
    float4 a = ((const float4*)t1)[i];
    float4 b = ((const float4*)t3)[i];
    float v[4];
    v[0] = a.x / (1.f + __expf(-a.x)) * b.x;
    v[1] = a.y / (1.f + __expf(-a.y)) * b.y;
    v[2] = a.z / (1.f + __expf(-a.z)) * b.z;
    v[3] = a.w / (1.f + __expf(-a.w)) * b.w;
    float h[4];
#pragma unroll
    for (int j=0;j<4;j++) h[j] = __bfloat162float(__float2bfloat16_rn(v[j]));
    ((uint2*)oh)[i] = make_uint2(packbf(h[0],h[1]), packbf(h[2],h[3]));
    ((uint2*)ol)[i] = make_uint2(packbf(v[0]-h[0],v[1]-h[1]), packbf(v[2]-h[2],v[3]-h[3]));
}

// ---------------- edge bucketing (single block, smem-staged) -------------
__global__ void bucket_kernel(const int* __restrict__ w)
{
    __shared__ int s_dst[NEDGE];        // 32 KB
    __shared__ int s_is64;
    __shared__ int s_cnt[LLOG];
    __shared__ int s_st[LLOG+1];
    int t = threadIdx.x;
    if (t == 0) {
        int z = 0;
        for (int i=1;i<64;i+=2) z |= w[i];
        s_is64 = (z == 0);
    }
    __syncthreads();
    int is64 = s_is64;
    for (int e=t; e<NEDGE; e+=256)
        s_dst[e] = is64 ? w[2*NEDGE + 2*e] : w[NEDGE + e];
    __syncthreads();
    int cnt = 0;
    for (int e=0;e<NEDGE;e++) cnt += (s_dst[e] == t);
    s_cnt[t] = cnt;
    __syncthreads();
    if (t == 0) {
        int acc = 0;
        for (int l=0;l<LLOG;l++) { s_st[l] = acc; acc += s_cnt[l]; }
        s_st[LLOG] = acc;
    }
    __syncthreads();
    g_start[t] = s_st[t];
    if (t == 0) g_start[LLOG] = s_st[LLOG];
    int idx = s_st[t];
    for (int e=0;e<NEDGE;e++) {
        if (s_dst[e] == t) {
            int src = is64 ? w[2*e] : w[e];
            g_order[idx++] = src;
        }
    }
}

// ---------------- scatter-multiply ----------------
__global__ __launch_bounds__(256) void scatterprod_kernel(
    const float* __restrict__ x3, float* __restrict__ lout)
{
    int l = blockIdx.x, bc = blockIdx.y, d = threadIdx.x;
    int s = g_start[l], e = g_start[l+1];
    float p = 1.f;
    const float* base = x3 + (size_t)bc*NSEQ*DMODEL + d;
    for (int i=s; i<e; i++) p *= base[(size_t)g_order[i]*DMODEL];
    lout[((size_t)bc*LLOG + l)*DMODEL + d] = p;
}

// ---------------- head ----------------
__global__ __launch_bounds__(256) void head_kernel(
    const float* __restrict__ l2, const float* __restrict__ hw,
    const float* __restrict__ hb, float* __restrict__ out)
{
    int tok  = blockIdx.x*8 + (threadIdx.x >> 5);
    int lane = threadIdx.x & 31;
    const float* p = l2 + (size_t)tok*DMODEL;
    float s = 0.f;
#pragma unroll
    for (int i=0;i<8;i++) s += p[lane + 32*i]*hw[lane + 32*i];
#pragma unroll
    for (int off=16; off; off>>=1) s += __shfl_xor_sync(0xffffffffu, s, off);
    if (lane == 0) out[tok] = s + hb[0];
}

// ---------------- host orchestration ----------------
// weight offsets in g_whi/g_wlo (elements)
#define WO_INPROJ 0
#define WO_OUT    196608
#define WO_FW1    262144
#define WO_FW3    458752
#define WO_FW2    655360
#define WO_DW1    851968
#define WO_DW3    1048576
#define WO_DW2    1245184
#define WO_LW1    1441792
#define WO_LW3    1638400
#define WO_LW2    1835008

static __nv_bfloat16 *h_whi, *h_wlo;

static inline void launch_bgemm(int epi, const __nv_bfloat16* Ah, const __nv_bfloat16* Al,
                                size_t woff, const float* bias, const float* resid,
                                float* C, __nv_bfloat16* Ch, __nv_bfloat16* Cl,
                                int M, int Nn, int K)
{
    dim3 grid(Nn/128, M/128);
    const __nv_bfloat16* Wh = h_whi + woff;
    const __nv_bfloat16* Wl = h_wlo + woff;
    if (epi == 0) {
        cudaFuncSetAttribute(bgemm_kernel<0>, cudaFuncAttributeMaxDynamicSharedMemorySize, BG_SMEM);
        bgemm_kernel<0><<<grid,256,BG_SMEM>>>(Ah,Al,Wh,Wl,bias,resid,C,Ch,Cl,M,Nn,K);
    } else if (epi == 1) {
        cudaFuncSetAttribute(bgemm_kernel<1>, cudaFuncAttributeMaxDynamicSharedMemorySize, BG_SMEM);
        bgemm_kernel<1><<<grid,256,BG_SMEM>>>(Ah,Al,Wh,Wl,bias,resid,C,Ch,Cl,M,Nn,K);
    } else if (epi == 2) {
        cudaFuncSetAttribute(bgemm_kernel<2>, cudaFuncAttributeMaxDynamicSharedMemorySize, BG_SMEM);
        bgemm_kernel<2><<<grid,256,BG_SMEM>>>(Ah,Al,Wh,Wl,bias,resid,C,Ch,Cl,M,Nn,K);
    } else {
        cudaFuncSetAttribute(bgemm_kernel<3>, cudaFuncAttributeMaxDynamicSharedMemorySize, BG_SMEM);
        bgemm_kernel<3><<<grid,256,BG_SMEM>>>(Ah,Al,Wh,Wl,bias,resid,C,Ch,Cl,M,Nn,K);
    }
}

extern "C" void kernel_launch(void* const* d_in, const int* in_sizes, int n_in,
                              void* d_out, int out_size)
{
    (void)in_sizes; (void)n_in; (void)out_size;
    const float* v           = (const float*)d_in[0];
    const int*   d2l         = (const int*)  d_in[1];
    const float* attn_norm_w = (const float*)d_in[2];
    const float* in_proj_w   = (const float*)d_in[3];
    const float* in_proj_b   = (const float*)d_in[4];
    const float* out_w       = (const float*)d_in[5];
    const float* out_b       = (const float*)d_in[6];
    const float* ffn_norm_w  = (const float*)d_in[7];
    const float* ffn_w1      = (const float*)d_in[8];
    const float* ffn_w2      = (const float*)d_in[9];
    const float* ffn_w3      = (const float*)d_in[10];
    const float* du_norm_w   = (const float*)d_in[11];
    const float* du_w1       = (const float*)d_in[12];
    const float* du_w2       = (const float*)d_in[13];
    const float* du_w3       = (const float*)d_in[14];
    const float* lu_norm_w   = (const float*)d_in[15];
    const float* lu_w1       = (const float*)d_in[16];
    const float* lu_w2       = (const float*)d_in[17];
    const float* lu_w3       = (const float*)d_in[18];
    const float* head_w      = (const float*)d_in[19];
    const float* head_b      = (const float*)d_in[20];
    float* out = (float*)d_out;

    float *buf1, *buf2, *a, *x2, *x3, *lb, *l2;
    __nv_bfloat16 *xnh, *xnl, *qkvh, *qkvl, *t1h, *t1l, *aoh, *aol;
    cudaGetSymbolAddress((void**)&buf1, g_buf1);
    cudaGetSymbolAddress((void**)&buf2, g_buf2);
    cudaGetSymbolAddress((void**)&a,    g_a);
    cudaGetSymbolAddress((void**)&x2,   g_x2);
    cudaGetSymbolAddress((void**)&x3,   g_x3);
    cudaGetSymbolAddress((void**)&lb,   g_l);
    cudaGetSymbolAddress((void**)&l2,   g_l2);
    cudaGetSymbolAddress((void**)&xnh,  g_xnh);
    cudaGetSymbolAddress((void**)&xnl,  g_xnl);
    cudaGetSymbolAddress((void**)&qkvh, g_qkvh);
    cudaGetSymbolAddress((void**)&qkvl, g_qkvl);
    cudaGetSymbolAddress((void**)&t1h,  g_t1h);
    cudaGetSymbolAddress((void**)&t1l,  g_t1l);
    cudaGetSymbolAddress((void**)&aoh,  g_aoh);
    cudaGetSymbolAddress((void**)&aol,  g_aol);
    cudaGetSymbolAddress((void**)&h_whi, g_whi);
    cudaGetSymbolAddress((void**)&h_wlo, g_wlo);

    // 0) all weight splits in one launch (packed order matches WO_* offsets)
    wconv_all_kernel<<<(WTOT/4+255)/256,256>>>(
        in_proj_w, out_w, ffn_w1, ffn_w3, ffn_w2,
        du_w1, du_w3, du_w2, lu_w1, lu_w3, lu_w2,
        h_whi, h_wlo);
    bucket_kernel<<<1,256>>>(d2l);

    // 1) attn pre-norm -> bf16 hi/lo
    rms_kernel<<<NTOK/8,256>>>(v, attn_norm_w, xnh, xnl);
    // 2) qkv projection -> bf16 hi/lo
    launch_bgemm(3, xnh, xnl, WO_INPROJ, in_proj_b, nullptr, nullptr, qkvh, qkvl, NTOK, HID, DMODEL);
    // 3) mma attention -> bf16 hi/lo
    { dim3 g(NSEQ/128, NHEAD, BC); attn_mma_kernel<<<g,256>>>(qkvh, qkvl, aoh, aol); }
    // 4) out projection + bias + residual v -> a (fp32)
    launch_bgemm(1, aoh, aol, WO_OUT, out_b, v, a, nullptr, nullptr, NTOK, DMODEL, DMODEL);
    // 5) FFN
    rms_kernel<<<NTOK/8,256>>>(a, ffn_norm_w, xnh, xnl);
    launch_bgemm(0, xnh, xnl, WO_FW1, nullptr, nullptr, buf1, nullptr, nullptr, NTOK, HID, DMODEL);
    launch_bgemm(0, xnh, xnl, WO_FW3, nullptr, nullptr, buf2, nullptr, nullptr, NTOK, HID, DMODEL);
    swiglu_kernel<<<(NTOK*HID/4+255)/256,256>>>(buf1, buf2, t1h, t1l, NTOK*HID/4);
    launch_bgemm(1, t1h, t1l, WO_FW2, nullptr, a, x2, nullptr, nullptr, NTOK, DMODEL, HID);
    // 6) du block with tanh
    rms_kernel<<<NTOK/8,256>>>(x2, du_norm_w, xnh, xnl);
    launch_bgemm(0, xnh, xnl, WO_DW1, nullptr, nullptr, buf1, nullptr, nullptr, NTOK, HID, DMODEL);
    launch_bgemm(0, xnh, xnl, WO_DW3, nullptr, nullptr, buf2, nullptr, nullptr, NTOK, HID, DMODEL);
    swiglu_kernel<<<(NTOK*HID/4+255)/256,256>>>(buf1, buf2, t1h, t1l, NTOK*HID/4);
    launch_bgemm(2, t1h, t1l, WO_DW2, nullptr, x2, x3, nullptr, nullptr, NTOK, DMODEL, HID);
    // 7) scatter-multiply into l
    { dim3 g(LLOG, BC); scatterprod_kernel<<<g,256>>>(x3, lb); }
    // 8) lu block
    rms_kernel<<<NTOKL/8,256>>>(lb, lu_norm_w, xnh, xnl);
    launch_bgemm(0, xnh, xnl, WO_LW1, nullptr, nullptr, buf1, nullptr, nullptr, NTOKL, HID, DMODEL);
    launch_bgemm(0, xnh, xnl, WO_LW3, nullptr, nullptr, buf2, nullptr, nullptr, NTOKL, HID, DMODEL);
    swiglu_kernel<<<(NTOKL*HID/4+255)/256,256>>>(buf1, buf2, t1h, t1l, NTOKL*HID/4);
    launch_bgemm(1, t1h, t1l, WO_LW2, nullptr, lb, l2, nullptr, nullptr, NTOKL, DMODEL, HID);
    // 9) head
    head_kernel<<<NTOKL/8,256>>>(l2, head_w, head_b, out);
}

// round 10
// speedup vs baseline: 2.4616x; 1.0020x over previous
#include <cuda_runtime.h>
#include <cuda_bf16.h>
#include <math.h>
#include <stdint.h>

// ---------------- problem constants ----------------
#define BC    32
#define NSEQ  1024
#define DMODEL 256
#define NHEAD 8
#define DHEAD 32
#define HID   768
#define NEDGE 8192
#define LLOG  256
#define NTOK  (BC*NSEQ)   // 32768
#define NTOKL (BC*LLOG)   // 8192
#define WTOT  2031616     // total weight elements

// ---------------- scratch (__device__ globals; no allocs) ----------------
__device__ float g_buf1[NTOK*HID];
__device__ float g_buf2[NTOK*HID];
__device__ float g_a   [NTOK*DMODEL];
__device__ float g_x2  [NTOK*DMODEL];
__device__ float g_x3  [NTOK*DMODEL];
__device__ float g_l   [NTOKL*DMODEL];
__device__ float g_l2  [NTOKL*DMODEL];
__device__ int   g_start[LLOG+1];
__device__ int   g_order[NEDGE];
__device__ __nv_bfloat16 g_xnh[NTOK*DMODEL], g_xnl[NTOK*DMODEL];
__device__ __nv_bfloat16 g_qkvh[NTOK*HID],  g_qkvl[NTOK*HID];
__device__ __nv_bfloat16 g_t1h[NTOK*HID],   g_t1l[NTOK*HID];
__device__ __nv_bfloat16 g_aoh[NTOK*DMODEL], g_aol[NTOK*DMODEL];
__device__ __nv_bfloat16 g_whi[WTOT], g_wlo[WTOT];

// ================= mma helpers =================
__device__ __forceinline__ uint32_t smem_u32(const void* p) {
    uint32_t a;
    asm("{ .reg .u64 t; cvta.to.shared.u64 t, %1; cvt.u32.u64 %0, t; }"
        : "=r"(a) : "l"(p));
    return a;
}
__device__ __forceinline__ void ldsm4(uint32_t addr, uint32_t& r0, uint32_t& r1,
                                      uint32_t& r2, uint32_t& r3) {
    asm volatile("ldmatrix.sync.aligned.m8n8.x4.shared.b16 {%0,%1,%2,%3}, [%4];"
                 : "=r"(r0), "=r"(r1), "=r"(r2), "=r"(r3) : "r"(addr));
}
__device__ __forceinline__ void ldsm4t(uint32_t addr, uint32_t& r0, uint32_t& r1,
                                       uint32_t& r2, uint32_t& r3) {
    asm volatile("ldmatrix.sync.aligned.m8n8.x4.trans.shared.b16 {%0,%1,%2,%3}, [%4];"
                 : "=r"(r0), "=r"(r1), "=r"(r2), "=r"(r3) : "r"(addr));
}
__device__ __forceinline__ void mma16816(float* d, uint32_t a0, uint32_t a1,
                                         uint32_t a2, uint32_t a3,
                                         uint32_t b0, uint32_t b1) {
    asm volatile(
        "mma.sync.aligned.m16n8k16.row.col.f32.bf16.bf16.f32 "
        "{%0,%1,%2,%3}, {%4,%5,%6,%7}, {%8,%9}, {%0,%1,%2,%3};"
        : "+f"(d[0]), "+f"(d[1]), "+f"(d[2]), "+f"(d[3])
        : "r"(a0), "r"(a1), "r"(a2), "r"(a3), "r"(b0), "r"(b1));
}
__device__ __forceinline__ uint32_t packbf(float x, float y) {
    __nv_bfloat162 h = __floats2bfloat162_rn(x, y);
    return *(uint32_t*)&h;
}
__device__ __forceinline__ void cpasync16(uint32_t saddr, const void* g) {
    asm volatile("cp.async.cg.shared.global [%0], [%1], 16;" :: "r"(saddr), "l"(g));
}
__device__ __forceinline__ void cpcommit() {
    asm volatile("cp.async.commit_group;");
}

// ---------------- batched weight split ----------------
__global__ __launch_bounds__(256) void wconv_all_kernel(
    const float* __restrict__ s0, const float* __restrict__ s1,
    const float* __restrict__ s2, const float* __restrict__ s3,
    const float* __restrict__ s4, const float* __restrict__ s5,
    const float* __restrict__ s6, const float* __restrict__ s7,
    const float* __restrict__ s8, const float* __restrict__ s9,
    const float* __restrict__ s10,
    __nv_bfloat16* __restrict__ dh, __nv_bfloat16* __restrict__ dl)
{
    int i = blockIdx.x*256 + threadIdx.x;
    const int B0=49152, B1=65536, B2=114688, B3=163840, B4=212992, B5=262144,
              B6=311296, B7=360448, B8=409600, B9=458752, B10=507904;
    if (i >= B10) return;
    const float* src; int base;
    if      (i < B0) { src = s0;  base = 0;  }
    else if (i < B1) { src = s1;  base = B0; }
    else if (i < B2) { src = s2;  base = B1; }
    else if (i < B3) { src = s3;  base = B2; }
    else if (i < B4) { src = s4;  base = B3; }
    else if (i < B5) { src = s5;  base = B4; }
    else if (i < B6) { src = s6;  base = B5; }
    else if (i < B7) { src = s7;  base = B6; }
    else if (i < B8) { src = s8;  base = B7; }
    else if (i < B9) { src = s9;  base = B8; }
    else             { src = s10; base = B9; }
    float4 v = ((const float4*)src)[i - base];
    float h0=__bfloat162float(__float2bfloat16_rn(v.x));
    float h1=__bfloat162float(__float2bfloat16_rn(v.y));
    float h2=__bfloat162float(__float2bfloat16_rn(v.z));
    float h3=__bfloat162float(__float2bfloat16_rn(v.w));
    ((uint2*)dh)[i] = make_uint2(packbf(h0,h1), packbf(h2,h3));
    ((uint2*)dl)[i] = make_uint2(packbf(v.x-h0,v.y-h1), packbf(v.z-h2,v.w-h3));
}

// ---------------- bf16 GEMM: C[M,N] = (Ah+Al)(Wh+Wl)^T 3-term ----------
// CTA 128x128, BK=32, 256 threads (2x4 warps, warp tile 64x32), 3-pass MMA.
#define BGS 40
#define BARR (128*BGS)
#define BBUFE (4*BARR)
#define BG_SMEM (2*BBUFE*2)

template<int EPI>
__global__ __launch_bounds__(256) void bgemm_kernel(
    const __nv_bfloat16* __restrict__ Ah, const __nv_bfloat16* __restrict__ Al,
    const __nv_bfloat16* __restrict__ Wh, const __nv_bfloat16* __restrict__ Wl,
    const float* __restrict__ bias, const float* __restrict__ resid,
    float* __restrict__ C, __nv_bfloat16* __restrict__ Ch,
    __nv_bfloat16* __restrict__ Cl, int M, int Nn, int K)
{
    extern __shared__ __nv_bfloat16 sm[];
    const int t = threadIdx.x, lane = t & 31, wid = t >> 5;
    const int wm = wid >> 2, wn = wid & 3;
    const int bm = blockIdx.y * 128, bn = blockIdx.x * 128;
    const uint32_t sbase = smem_u32(sm);
    const int nc = K / 32;

    float acc[4][4][4];
#pragma unroll
    for (int i=0;i<4;i++)
#pragma unroll
        for (int j=0;j<4;j++)
#pragma unroll
            for (int e=0;e<4;e++) acc[i][j][e]=0.f;

    // per-thread loader bases (hoisted 64-bit math)
    const int lrow = t >> 2, lcol8 = (t & 3) * 8;
    const __nv_bfloat16* pAh0 = Ah + (size_t)(bm + lrow)*K + lcol8;
    const __nv_bfloat16* pAl0 = Al + (size_t)(bm + lrow)*K + lcol8;
    const __nv_bfloat16* pWh0 = Wh + (size_t)(bn + lrow)*K + lcol8;
    const __nv_bfloat16* pWl0 = Wl + (size_t)(bn + lrow)*K + lcol8;
    const size_t rstep = (size_t)64*K;
    const uint32_t s0 = sbase + (uint32_t)(lrow*BGS + lcol8)*2;
    const uint32_t s1 = sbase + (uint32_t)((lrow+64)*BGS + lcol8)*2;

    auto issue = [&](int c) {
        uint32_t bs = (uint32_t)(c & 1)*(BBUFE*2);
        int off = c*32;
        cpasync16(bs + s0 + 0*BARR*2, pAh0 + off);
        cpasync16(bs + s1 + 0*BARR*2, pAh0 + rstep + off);
        cpasync16(bs + s0 + 1*BARR*2, pAl0 + off);
        cpasync16(bs + s1 + 1*BARR*2, pAl0 + rstep + off);
        cpasync16(bs + s0 + 2*BARR*2, pWh0 + off);
        cpasync16(bs + s1 + 2*BARR*2, pWh0 + rstep + off);
        cpasync16(bs + s0 + 3*BARR*2, pWl0 + off);
        cpasync16(bs + s1 + 3*BARR*2, pWl0 + rstep + off);
        cpcommit();
    };
    issue(0);

    for (int c = 0; c < nc; c++) {
        if (c + 1 < nc) {
            issue(c + 1);
            asm volatile("cp.async.wait_group 1;");
        } else {
            asm volatile("cp.async.wait_group 0;");
        }
        __syncthreads();
        uint32_t base = sbase + (uint32_t)(c & 1)*(BBUFE*2);
#pragma unroll
        for (int ks = 0; ks < 2; ks++) {
            uint32_t ahf[4][4], alf[4][4], bhf[2][4], blf[2][4];
            int rl = lane & 15, ch = (lane >> 4) * 8;
            int col = ks*16 + ch;
#pragma unroll
            for (int mt=0; mt<4; mt++) {
                int row = wm*64 + mt*16 + rl;
                uint32_t o = (uint32_t)(row*BGS + col)*2;
                ldsm4(base + 0*BARR*2 + o, ahf[mt][0],ahf[mt][1],ahf[mt][2],ahf[mt][3]);
                ldsm4(base + 1*BARR*2 + o, alf[mt][0],alf[mt][1],alf[mt][2],alf[mt][3]);
            }
#pragma unroll
            for (int g=0; g<2; g++) {
                int row = wn*32 + g*16 + rl;
                uint32_t o = (uint32_t)(row*BGS + col)*2;
                ldsm4(base + 2*BARR*2 + o, bhf[g][0],bhf[g][1],bhf[g][2],bhf[g][3]);
                ldsm4(base + 3*BARR*2 + o, blf[g][0],blf[g][1],blf[g][2],blf[g][3]);
            }
            // pass 1: Ahi * Bhi  (16 independent MMAs)
#pragma unroll
            for (int mt=0; mt<4; mt++)
#pragma unroll
                for (int g=0; g<2; g++)
#pragma unroll
                    for (int sub=0; sub<2; sub++) {
                        int nt = g*2 + sub;
                        uint32_t h0 = sub ? bhf[g][1] : bhf[g][0];
                        uint32_t h1 = sub ? bhf[g][3] : bhf[g][2];
                        mma16816(acc[mt][nt], ahf[mt][0],ahf[mt][1],ahf[mt][2],ahf[mt][3], h0,h1);
                    }
            // pass 2: Ahi * Blo
#pragma unroll
            for (int mt=0; mt<4; mt++)
#pragma unroll
                for (int g=0; g<2; g++)
#pragma unroll
                    for (int sub=0; sub<2; sub++) {
                        int nt = g*2 + sub;
                        uint32_t l0 = sub ? blf[g][1] : blf[g][0];
                        uint32_t l1 = sub ? blf[g][3] : blf[g][2];
                        mma16816(acc[mt][nt], ahf[mt][0],ahf[mt][1],ahf[mt][2],ahf[mt][3], l0,l1);
                    }
            // pass 3: Alo * Bhi
#pragma unroll
            for (int mt=0; mt<4; mt++)
#pragma unroll
                for (int g=0; g<2; g++)
#pragma unroll
                    for (int sub=0; sub<2; sub++) {
                        int nt = g*2 + sub;
                        uint32_t h0 = sub ? bhf[g][1] : bhf[g][0];
                        uint32_t h1 = sub ? bhf[g][3] : bhf[g][2];
                        mma16816(acc[mt][nt], alf[mt][0],alf[mt][1],alf[mt][2],alf[mt][3], h0,h1);
                    }
        }
        __syncthreads();
    }

    // epilogue
#pragma unroll
    for (int mt=0; mt<4; mt++)
#pragma unroll
        for (int nt=0; nt<4; nt++) {
            int m0 = bm + wm*64 + mt*16 + (lane >> 2);
            int n0 = bn + wn*32 + nt*8 + (lane & 3)*2;
            float2 bb = make_float2(0.f, 0.f);
            if (bias) bb = *(const float2*)(bias + n0);
            float v[4] = {acc[mt][nt][0]+bb.x, acc[mt][nt][1]+bb.y,
                          acc[mt][nt][2]+bb.x, acc[mt][nt][3]+bb.y};
            size_t i0 = (size_t)m0*Nn + n0;
            size_t i1 = (size_t)(m0+8)*Nn + n0;
            if (EPI == 3) {
                float h0=__bfloat162float(__float2bfloat16_rn(v[0]));
                float h1=__bfloat162float(__float2bfloat16_rn(v[1]));
                float h2=__bfloat162float(__float2bfloat16_rn(v[2]));
                float h3=__bfloat162float(__float2bfloat16_rn(v[3]));
                *(uint32_t*)(Ch + i0) = packbf(h0, h1);
                *(uint32_t*)(Cl + i0) = packbf(v[0]-h0, v[1]-h1);
                *(uint32_t*)(Ch + i1) = packbf(h2, h3);
                *(uint32_t*)(Cl + i1) = packbf(v[2]-h2, v[3]-h3);
            } else {
                if (EPI >= 1) {
                    float2 r0 = *(const float2*)(resid + i0);
                    float2 r1 = *(const float2*)(resid + i1);
                    v[0]+=r0.x; v[1]+=r0.y; v[2]+=r1.x; v[3]+=r1.y;
                }
                if (EPI == 2) {
                    v[0]=tanhf(v[0]); v[1]=tanhf(v[1]);
                    v[2]=tanhf(v[2]); v[3]=tanhf(v[3]);
                }
                *(float2*)(C + i0) = make_float2(v[0], v[1]);
                *(float2*)(C + i1) = make_float2(v[2], v[3]);
            }
        }
}

// ---------------- mma flash attention: 128q/CTA, kv tiles 64, bf16x3 -------
__global__ __launch_bounds__(256) void attn_mma_kernel(
    const __nv_bfloat16* __restrict__ qh, const __nv_bfloat16* __restrict__ ql,
    __nv_bfloat16* __restrict__ aoh, __nv_bfloat16* __restrict__ aol)
{
    __shared__ __nv_bfloat16 sQ[2][128*40];
    __shared__ __nv_bfloat16 sK[2][64*40];
    __shared__ __nv_bfloat16 sV[2][64*40];
    const int qt = blockIdx.x, h = blockIdx.y, bc = blockIdx.z;
    const int t = threadIdx.x, lane = t & 31, w = t >> 5;
    const size_t tokb = (size_t)bc*NSEQ;
    const float scale = 0.17677669529663687f;

#pragma unroll
    for (int r=0;r<2;r++) {
        int f = t + r*256, row = f >> 2, c8 = (f & 3)*8;
        size_t g = (tokb + qt*128 + row)*HID + h*DHEAD + c8;
        *(uint4*)&sQ[0][row*40+c8] = *(const uint4*)(qh + g);
        *(uint4*)&sQ[1][row*40+c8] = *(const uint4*)(ql + g);
    }
    __syncthreads();

    uint32_t qfh[2][4], qfl[2][4];
    {
        const uint32_t q0 = smem_u32(sQ[0]), q1 = smem_u32(sQ[1]);
#pragma unroll
        for (int kc=0;kc<2;kc++) {
            int row = w*16 + (lane & 15), col = kc*16 + (lane >> 4)*8;
            uint32_t o2 = (uint32_t)(row*40 + col)*2;
            ldsm4(q0 + o2, qfh[kc][0],qfh[kc][1],qfh[kc][2],qfh[kc][3]);
            ldsm4(q1 + o2, qfl[kc][0],qfl[kc][1],qfl[kc][2],qfl[kc][3]);
        }
    }

    float o[4][4];
#pragma unroll
    for (int i=0;i<4;i++)
#pragma unroll
        for (int j=0;j<4;j++) o[i][j]=0.f;
    float mrun0=-1e30f, mrun1=-1e30f, lrun0=0.f, lrun1=0.f;
    const uint32_t k0b = smem_u32(sK[0]), k1b = smem_u32(sK[1]);
    const uint32_t v0b = smem_u32(sV[0]), v1b = smem_u32(sV[1]);

    for (int kt=0; kt<16; kt++) {
        __syncthreads();
        {
            int row = t >> 2, c8 = (t & 3)*8;
            size_t g = (tokb + kt*64 + row)*HID + h*DHEAD + c8;
            *(uint4*)&sK[0][row*40+c8] = *(const uint4*)(qh + g + DMODEL);
            *(uint4*)&sK[1][row*40+c8] = *(const uint4*)(ql + g + DMODEL);
            *(uint4*)&sV[0][row*40+c8] = *(const uint4*)(qh + g + 2*DMODEL);
            *(uint4*)&sV[1][row*40+c8] = *(const uint4*)(ql + g + 2*DMODEL);
        }
        __syncthreads();

        float S[8][4];
#pragma unroll
        for (int j=0;j<8;j++)
#pragma unroll
            for (int e=0;e<4;e++) S[j][e]=0.f;
#pragma unroll
        for (int kc=0;kc<2;kc++)
#pragma unroll
            for (int jp=0;jp<4;jp++) {
                int row = jp*16 + ((lane>>4)&1)*8 + (lane&7);
                int col = kc*16 + ((lane>>3)&1)*8;
                uint32_t o2 = (uint32_t)(row*40 + col)*2;
                uint32_t h0,h1,h2,h3, l0,l1,l2,l3;
                ldsm4(k0b + o2, h0,h1,h2,h3);
                ldsm4(k1b + o2, l0,l1,l2,l3);
                mma16816(S[2*jp],   qfh[kc][0],qfh[kc][1],qfh[kc][2],qfh[kc][3], h0,h1);
                mma16816(S[2*jp+1], qfh[kc][0],qfh[kc][1],qfh[kc][2],qfh[kc][3], h2,h3);
                mma16816(S[2*jp],   qfh[kc][0],qfh[kc][1],qfh[kc][2],qfh[kc][3], l0,l1);
                mma16816(S[2*jp+1], qfh[kc][0],qfh[kc][1],qfh[kc][2],qfh[kc][3], l2,l3);
                mma16816(S[2*jp],   qfl[kc][0],qfl[kc][1],qfl[kc][2],qfl[kc][3], h0,h1);
                mma16816(S[2*jp+1], qfl[kc][0],qfl[kc][1],qfl[kc][2],qfl[kc][3], h2,h3);
            }

        float mx0=-1e30f, mx1=-1e30f;
#pragma unroll
        for (int j=0;j<8;j++) {
            mx0 = fmaxf(mx0, fmaxf(S[j][0], S[j][1]));
            mx1 = fmaxf(mx1, fmaxf(S[j][2], S[j][3]));
        }
        mx0 *= scale; mx1 *= scale;
        mx0 = fmaxf(mx0, __shfl_xor_sync(0xffffffffu, mx0, 1));
        mx0 = fmaxf(mx0, __shfl_xor_sync(0xffffffffu, mx0, 2));
        mx1 = fmaxf(mx1, __shfl_xor_sync(0xffffffffu, mx1, 1));
        mx1 = fmaxf(mx1, __shfl_xor_sync(0xffffffffu, mx1, 2));
        float mn0 = fmaxf(mrun0, mx0), mn1 = fmaxf(mrun1, mx1);
        float a0 = __expf(mrun0 - mn0), a1 = __expf(mrun1 - mn1);
        mrun0 = mn0; mrun1 = mn1;
#pragma unroll
        for (int nt=0;nt<4;nt++) {
            o[nt][0]*=a0; o[nt][1]*=a0; o[nt][2]*=a1; o[nt][3]*=a1;
        }
        float rs0=0.f, rs1=0.f;
#pragma unroll
        for (int kc2=0;kc2<4;kc2++) {
            int j0 = 2*kc2;
            float p00=__expf(S[j0][0]*scale - mn0), p01=__expf(S[j0][1]*scale - mn0);
            float p02=__expf(S[j0][2]*scale - mn1), p03=__expf(S[j0][3]*scale - mn1);
            float p10=__expf(S[j0+1][0]*scale - mn0), p11=__expf(S[j0+1][1]*scale - mn0);
            float p12=__expf(S[j0+1][2]*scale - mn1), p13=__expf(S[j0+1][3]*scale - mn1);
            rs0 += p00+p01+p10+p11;
            rs1 += p02+p03+p12+p13;
            float q00=__bfloat162float(__float2bfloat16_rn(p00));
            float q01=__bfloat162float(__float2bfloat16_rn(p01));
            float q02=__bfloat162float(__float2bfloat16_rn(p02));
            float q03=__bfloat162float(__float2bfloat16_rn(p03));
            float q10=__bfloat162float(__float2bfloat16_rn(p10));
            float q11=__bfloat162float(__float2bfloat16_rn(p11));
            float q12=__bfloat162float(__float2bfloat16_rn(p12));
            float q13=__bfloat162float(__float2bfloat16_rn(p13));
            uint32_t aph[4] = {packbf(q00,q01), packbf(q02,q03),
                               packbf(q10,q11), packbf(q12,q13)};
            uint32_t apl[4] = {packbf(p00-q00,p01-q01), packbf(p02-q02,p03-q03),
                               packbf(p10-q10,p11-q11), packbf(p12-q12,p13-q13)};
#pragma unroll
            for (int g=0; g<2; g++) {
                int row = kc2*16 + ((lane>>3)&1)*8 + (lane&7);
                int col = g*16 + ((lane>>4)&1)*8;
                uint32_t o2 = (uint32_t)(row*40 + col)*2;
                uint32_t vh0,vh1,vh2,vh3, vl0,vl1,vl2,vl3;
                ldsm4t(v0b + o2, vh0,vh1,vh2,vh3);
                ldsm4t(v1b + o2, vl0,vl1,vl2,vl3);
                mma16816(o[2*g],   aph[0],aph[1],aph[2],aph[3], vh0,vh1);
                mma16816(o[2*g+1], aph[0],aph[1],aph[2],aph[3], vh2,vh3);
                mma16816(o[2*g],   aph[0],aph[1],aph[2],aph[3], vl0,vl1);
                mma16816(o[2*g+1], aph[0],aph[1],aph[2],aph[3], vl2,vl3);
                mma16816(o[2*g],   apl[0],apl[1],apl[2],apl[3], vh0,vh1);
                mma16816(o[2*g+1], apl[0],apl[1],apl[2],apl[3], vh2,vh3);
            }
        }
        rs0 += __shfl_xor_sync(0xffffffffu, rs0, 1);
        rs0 += __shfl_xor_sync(0xffffffffu, rs0, 2);
        rs1 += __shfl_xor_sync(0xffffffffu, rs1, 1);
        rs1 += __shfl_xor_sync(0xffffffffu, rs1, 2);
        lrun0 = lrun0*a0 + rs0;
        lrun1 = lrun1*a1 + rs1;
    }

    float inv0 = 1.f/lrun0, inv1 = 1.f/lrun1;
    int r0 = qt*128 + w*16 + (lane >> 2);
#pragma unroll
    for (int nt=0; nt<4; nt++) {
        int d = h*DHEAD + nt*8 + (lane & 3)*2;
        size_t i0 = (tokb + r0)*DMODEL + d;
        size_t i1 = (tokb + r0 + 8)*DMODEL + d;
        float v0 = o[nt][0]*inv0, v1 = o[nt][1]*inv0;
        float v2 = o[nt][2]*inv1, v3 = o[nt][3]*inv1;
        float h0=__bfloat162float(__float2bfloat16_rn(v0));
        float h1=__bfloat162float(__float2bfloat16_rn(v1));
        float h2=__bfloat162float(__float2bfloat16_rn(v2));
        float h3=__bfloat162float(__float2bfloat16_rn(v3));
        *(uint32_t*)(aoh + i0) = packbf(h0, h1);
        *(uint32_t*)(aol + i0) = packbf(v0-h0, v1-h1);
        *(uint32_t*)(aoh + i1) = packbf(h2, h3);
        *(uint32_t*)(aol + i1) = packbf(v2-h2, v3-h3);
    }
}

// ---------------- RMS norm ----------------
__global__ __launch_bounds__(256) void rms_kernel(
    const float* __restrict__ x, const float* __restrict__ w,
    __nv_bfloat16* __restrict__ yh, __nv_bfloat16* __restrict__ yl)
{
    int tok  = blockIdx.x*8 + (threadIdx.x >> 5);
    int lane = threadIdx.x & 31;
    const float* xp = x + (size_t)tok*DMODEL;
    float4 a = *(const float4*)(xp + lane*4);
    float4 b = *(const float4*)(xp + 128 + lane*4);
    float ss = a.x*a.x + a.y*a.y + a.z*a.z + a.w*a.w
             + b.x*b.x + b.y*b.y + b.z*b.z + b.w*b.w;
#pragma unroll
    for (int off=16; off; off>>=1) ss += __shfl_xor_sync(0xffffffffu, ss, off);
    float r = rsqrtf(ss*(1.0f/DMODEL) + 1e-5f);
    float4 wa = *(const float4*)(w + lane*4);
    float4 wb = *(const float4*)(w + 128 + lane*4);
    float va[8] = {a.x*r*wa.x, a.y*r*wa.y, a.z*r*wa.z, a.w*r*wa.w,
                   b.x*r*wb.x, b.y*r*wb.y, b.z*r*wb.z, b.w*r*wb.w};
    size_t o0 = (size_t)tok*DMODEL + lane*4;
    size_t o1 = o0 + 128;
    float h[8];
#pragma unroll
    for (int i=0;i<8;i++) h[i] = __bfloat162float(__float2bfloat16_rn(va[i]));
    *(uint2*)(yh + o0) = make_uint2(packbf(h[0],h[1]), packbf(h[2],h[3]));
    *(uint2*)(yh + o1) = make_uint2(packbf(h[4],h[5]), packbf(h[6],h[7]));
    *(uint2*)(yl + o0) = make_uint2(packbf(va[0]-h[0],va[1]-h[1]), packbf(va[2]-h[2],va[3]-h[3]));
    *(uint2*)(yl + o1) = make_uint2(packbf(va[4]-h[4],va[5]-h[5]), packbf(va[6]-h[6],va[7]-h[7]));
}

// ---------------- swiglu ----------------
__global__ __launch_bounds__(256) void swiglu_kernel(
    const float* __restrict__ t1, const float* __restrict__ t3,
    __nv_bfloat16* __restrict__ oh, __nv_bfloat16* __restrict__ ol, int n4)
{
    int i = blockIdx.x*256 + threadIdx.x;
    if (i >= n4) return;
    float4 a = ((const float4*)t1)[i];
    float4 b = ((const float4*)t3)[i];
    float v[4];
    v[0] = a.x / (1.f + __expf(-a.x)) * b.x;
    v[1] = a.y / (1.f + __expf(-a.y)) * b.y;
    v[2] = a.z / (1.f + __expf(-a.z)) * b.z;
    v[3] = a.w / (1.f + __expf(-a.w)) * b.w;
    float h[4];
#pragma unroll
    for (int j=0;j<4;j++) h[j] = __bfloat162float(__float2bfloat16_rn(v[j]));
    ((uint2*)oh)[i] = make_uint2(packbf(h[0],h[1]), packbf(h[2],h[3]));
    ((uint2*)ol)[i] = make_uint2(packbf(v[0]-h[0],v[1]-h[1]), packbf(v[2]-h[2],v[3]-h[3]));
}

// ---------------- edge bucketing ----------------
__global__ void bucket_kernel(const int* __restrict__ w)
{
    __shared__ int s_dst[NEDGE];
    __shared__ int s_is64;
    __shared__ int s_cnt[LLOG];
    __shared__ int s_st[LLOG+1];
    int t = threadIdx.x;
    if (t == 0) {
        int z = 0;
        for (int i=1;i<64;i+=2) z |= w[i];
        s_is64 = (z == 0);
    }
    __syncthreads();
    int is64 = s_is64;
    for (int e=t; e<NEDGE; e+=256)
        s_dst[e] = is64 ? w[2*NEDGE + 2*e] : w[NEDGE + e];
    __syncthreads();
    int cnt = 0;
    for (int e=0;e<NEDGE;e++) cnt += (s_dst[e] == t);
    s_cnt[t] = cnt;
    __syncthreads();
    if (t == 0) {
        int acc = 0;
        for (int l=0;l<LLOG;l++) { s_st[l] = acc; acc += s_cnt[l]; }
        s_st[LLOG] = acc;
    }
    __syncthreads();
    g_start[t] = s_st[t];
    if (t == 0) g_start[LLOG] = s_st[LLOG];
    int idx = s_st[t];
    for (int e=0;e<NEDGE;e++) {
        if (s_dst[e] == t) {
            int src = is64 ? w[2*e] : w[e];
            g_order[idx++] = src;
        }
    }
}

// ---------------- scatter-multiply ----------------
__global__ __launch_bounds__(256) void scatterprod_kernel(
    const float* __restrict__ x3, float* __restrict__ lout)
{
    int l = blockIdx.x, bc = blockIdx.y, d = threadIdx.x;
    int s = g_start[l], e = g_start[l+1];
    float p = 1.f;
    const float* base = x3 + (size_t)bc*NSEQ*DMODEL + d;
    for (int i=s; i<e; i++) p *= base[(size_t)g_order[i]*DMODEL];
    lout[((size_t)bc*LLOG + l)*DMODEL + d] = p;
}

// ---------------- head ----------------
__global__ __launch_bounds__(256) void head_kernel(
    const float* __restrict__ l2, const float* __restrict__ hw,
    const float* __restrict__ hb, float* __restrict__ out)
{
    int tok  = blockIdx.x*8 + (threadIdx.x >> 5);
    int lane = threadIdx.x & 31;
    const float* p = l2 + (size_t)tok*DMODEL;
    float s = 0.f;
#pragma unroll
    for (int i=0;i<8;i++) s += p[lane + 32*i]*hw[lane + 32*i];
#pragma unroll
    for (int off=16; off; off>>=1) s += __shfl_xor_sync(0xffffffffu, s, off);
    if (lane == 0) out[tok] = s + hb[0];
}

// ---------------- host orchestration ----------------
#define WO_INPROJ 0
#define WO_OUT    196608
#define WO_FW1    262144
#define WO_FW3    458752
#define WO_FW2    655360
#define WO_DW1    851968
#define WO_DW3    1048576
#define WO_DW2    1245184
#define WO_LW1    1441792
#define WO_LW3    1638400
#define WO_LW2    1835008

static __nv_bfloat16 *h_whi, *h_wlo;

static inline void launch_bgemm(int epi, const __nv_bfloat16* Ah, const __nv_bfloat16* Al,
                                size_t woff, const float* bias, const float* resid,
                                float* C, __nv_bfloat16* Ch, __nv_bfloat16* Cl,
                                int M, int Nn, int K)
{
    dim3 grid(Nn/128, M/128);
    const __nv_bfloat16* Wh = h_whi + woff;
    const __nv_bfloat16* Wl = h_wlo + woff;
    if (epi == 0) {
        cudaFuncSetAttribute(bgemm_kernel<0>, cudaFuncAttributeMaxDynamicSharedMemorySize, BG_SMEM);
        bgemm_kernel<0><<<grid,256,BG_SMEM>>>(Ah,Al,Wh,Wl,bias,resid,C,Ch,Cl,M,Nn,K);
    } else if (epi == 1) {
        cudaFuncSetAttribute(bgemm_kernel<1>, cudaFuncAttributeMaxDynamicSharedMemorySize, BG_SMEM);
        bgemm_kernel<1><<<grid,256,BG_SMEM>>>(Ah,Al,Wh,Wl,bias,resid,C,Ch,Cl,M,Nn,K);
    } else if (epi == 2) {
        cudaFuncSetAttribute(bgemm_kernel<2>, cudaFuncAttributeMaxDynamicSharedMemorySize, BG_SMEM);
        bgemm_kernel<2><<<grid,256,BG_SMEM>>>(Ah,Al,Wh,Wl,bias,resid,C,Ch,Cl,M,Nn,K);
    } else {
        cudaFuncSetAttribute(bgemm_kernel<3>, cudaFuncAttributeMaxDynamicSharedMemorySize, BG_SMEM);
        bgemm_kernel<3><<<grid,256,BG_SMEM>>>(Ah,Al,Wh,Wl,bias,resid,C,Ch,Cl,M,Nn,K);
    }
}

extern "C" void kernel_launch(void* const* d_in, const int* in_sizes, int n_in,
                              void* d_out, int out_size)
{
    (void)in_sizes; (void)n_in; (void)out_size;
    const float* v           = (const float*)d_in[0];
    const int*   d2l         = (const int*)  d_in[1];
    const float* attn_norm_w = (const float*)d_in[2];
    const float* in_proj_w   = (const float*)d_in[3];
    const float* in_proj_b   = (const float*)d_in[4];
    const float* out_w       = (const float*)d_in[5];
    const float* out_b       = (const float*)d_in[6];
    const float* ffn_norm_w  = (const float*)d_in[7];
    const float* ffn_w1      = (const float*)d_in[8];
    const float* ffn_w2      = (const float*)d_in[9];
    const float* ffn_w3      = (const float*)d_in[10];
    const float* du_norm_w   = (const float*)d_in[11];
    const float* du_w1       = (const float*)d_in[12];
    const float* du_w2       = (const float*)d_in[13];
    const float* du_w3       = (const float*)d_in[14];
    const float* lu_norm_w   = (const float*)d_in[15];
    const float* lu_w1       = (const float*)d_in[16];
    const float* lu_w2       = (const float*)d_in[17];
    const float* lu_w3       = (const float*)d_in[18];
    const float* head_w      = (const float*)d_in[19];
    const float* head_b      = (const float*)d_in[20];
    float* out = (float*)d_out;

    float *buf1, *buf2, *a, *x2, *x3, *lb, *l2;
    __nv_bfloat16 *xnh, *xnl, *qkvh, *qkvl, *t1h, *t1l, *aoh, *aol;
    cudaGetSymbolAddress((void**)&buf1, g_buf1);
    cudaGetSymbolAddress((void**)&buf2, g_buf2);
    cudaGetSymbolAddress((void**)&a,    g_a);
    cudaGetSymbolAddress((void**)&x2,   g_x2);
    cudaGetSymbolAddress((void**)&x3,   g_x3);
    cudaGetSymbolAddress((void**)&lb,   g_l);
    cudaGetSymbolAddress((void**)&l2,   g_l2);
    cudaGetSymbolAddress((void**)&xnh,  g_xnh);
    cudaGetSymbolAddress((void**)&xnl,  g_xnl);
    cudaGetSymbolAddress((void**)&qkvh, g_qkvh);
    cudaGetSymbolAddress((void**)&qkvl, g_qkvl);
    cudaGetSymbolAddress((void**)&t1h,  g_t1h);
    cudaGetSymbolAddress((void**)&t1l,  g_t1l);
    cudaGetSymbolAddress((void**)&aoh,  g_aoh);
    cudaGetSymbolAddress((void**)&aol,  g_aol);
    cudaGetSymbolAddress((void**)&h_whi, g_whi);
    cudaGetSymbolAddress((void**)&h_wlo, g_wlo);

    // 0) all weight splits in one launch
    wconv_all_kernel<<<(WTOT/4+255)/256,256>>>(
        in_proj_w, out_w, ffn_w1, ffn_w3, ffn_w2,
        du_w1, du_w3, du_w2, lu_w1, lu_w3, lu_w2,
        h_whi, h_wlo);
    bucket_kernel<<<1,256>>>(d2l);

    // 1) attn pre-norm
    rms_kernel<<<NTOK/8,256>>>(v, attn_norm_w, xnh, xnl);
    // 2) qkv projection
    launch_bgemm(3, xnh, xnl, WO_INPROJ, in_proj_b, nullptr, nullptr, qkvh, qkvl, NTOK, HID, DMODEL);
    // 3) attention
    { dim3 g(NSEQ/128, NHEAD, BC); attn_mma_kernel<<<g,256>>>(qkvh, qkvl, aoh, aol); }
    // 4) out projection + residual
    launch_bgemm(1, aoh, aol, WO_OUT, out_b, v, a, nullptr, nullptr, NTOK, DMODEL, DMODEL);
    // 5) FFN
    rms_kernel<<<NTOK/8,256>>>(a, ffn_norm_w, xnh, xnl);
    launch_bgemm(0, xnh, xnl, WO_FW1, nullptr, nullptr, buf1, nullptr, nullptr, NTOK, HID, DMODEL);
    launch_bgemm(0, xnh, xnl, WO_FW3, nullptr, nullptr, buf2, nullptr, nullptr, NTOK, HID, DMODEL);
    swiglu_kernel<<<(NTOK*HID/4+255)/256,256>>>(buf1, buf2, t1h, t1l, NTOK*HID/4);
    launch_bgemm(1, t1h, t1l, WO_FW2, nullptr, a, x2, nullptr, nullptr, NTOK, DMODEL, HID);
    // 6) du block with tanh
    rms_kernel<<<NTOK/8,256>>>(x2, du_norm_w, xnh, xnl);
    launch_bgemm(0, xnh, xnl, WO_DW1, nullptr, nullptr, buf1, nullptr, nullptr, NTOK, HID, DMODEL);
    launch_bgemm(0, xnh, xnl, WO_DW3, nullptr, nullptr, buf2, nullptr, nullptr, NTOK, HID, DMODEL);
    swiglu_kernel<<<(NTOK*HID/4+255)/256,256>>>(buf1, buf2, t1h, t1l, NTOK*HID/4);
    launch_bgemm(2, t1h, t1l, WO_DW2, nullptr, x2, x3, nullptr, nullptr, NTOK, DMODEL, HID);
    // 7) scatter-multiply
    { dim3 g(LLOG, BC); scatterprod_kernel<<<g,256>>>(x3, lb); }
    // 8) lu block
    rms_kernel<<<NTOKL/8,256>>>(lb, lu_norm_w, xnh, xnl);
    launch_bgemm(0, xnh, xnl, WO_LW1, nullptr, nullptr, buf1, nullptr, nullptr, NTOKL, HID, DMODEL);
    launch_bgemm(0, xnh, xnl, WO_LW3, nullptr, nullptr, buf2, nullptr, nullptr, NTOKL, HID, DMODEL);
    swiglu_kernel<<<(NTOKL*HID/4+255)/256,256>>>(buf1, buf2, t1h, t1l, NTOKL*HID/4);
    launch_bgemm(1, t1h, t1l, WO_LW2, nullptr, lb, l2, nullptr, nullptr, NTOKL, DMODEL, HID);
    // 9) head
    head_kernel<<<NTOKL/8,256>>>(l2, head_w, head_b, out);
}